// round 12
// baseline (speedup 1.0000x reference)
#include <cuda_runtime.h>
#include <cstdint>

#define BT   32
#define P    36
#define NTHR 256
typedef unsigned long long ull;

// ---------------- persistent device scratch ----------------
__device__ __align__(16) float g_W1T[784*128];   // [k][j] (phase 1)
__device__ __align__(16) float g_PA[40960];      // 8 slots x 16k x [ -M1T(128) | U1T(128) | W2T(64) ]
__device__ __align__(16) float g_PB[10240];      // 2 slots x 32k x [ -M2T(64)  | U2T(64)  | W3T(32) ]
__device__ __align__(16) float g_PC[2048];       // 32k x [ -M3T(32) | U3T(32) ]
__device__ __align__(16) float g_c1[128];
__device__ __align__(16) float g_c2[64];
__device__ __align__(16) float g_c3[32];
__device__ __align__(16) float g_XW[65536*128];  // xw, column-major per 32-row tile

// ---------------- helpers ----------------
__device__ __forceinline__ ull dup2(float x) {
    ull r; asm("mov.b64 %0, {%1, %1};" : "=l"(r) : "f"(x)); return r;
}
__device__ __forceinline__ void up2(ull v, float &lo, float &hi) {
    asm("mov.b64 {%0, %1}, %2;" : "=f"(lo), "=f"(hi) : "l"(v));
}
__device__ __forceinline__ void fma2(ull &d, ull a, ull b) {
    asm("fma.rn.f32x2 %0, %1, %2, %0;" : "+l"(d) : "l"(a), "l"(b));
}
// tanh(x) = 1 - 2/(1+e^{2x})  via MUFU.EX2 + MUFU.RCP (~1e-6 abs err)
__device__ __forceinline__ float ftanh(float x) {
    float e, r;
    asm("ex2.approx.ftz.f32 %0, %1;" : "=f"(e) : "f"(x * 2.8853900817779268f));
    asm("rcp.approx.ftz.f32 %0, %1;" : "=f"(r) : "f"(e + 1.0f));
    return fmaf(-2.0f, r, 1.0f);
}
__device__ __forceinline__ void addf4(float4 &v, int r, float d) {
    if (r == 0) v.x += d; else if (r == 1) v.y += d;
    else if (r == 2) v.z += d; else v.w += d;
}
__device__ __forceinline__ float getf4(const float4 &v, int r) {
    return (r == 0) ? v.x : (r == 1) ? v.y : (r == 2) ? v.z : v.w;
}

// ---- fused loop A: A=h1 chunk (K=16), B-panel row = [M1T|U1T|W2T] (320 fl/k)
// thread: 4 rows (i0..i0+3), cols j4..j4+3 (M1/U1) and j2..j2+1 (W2)
__device__ __forceinline__ void gemmA(const float* __restrict__ A,
                                      const float* __restrict__ Bp,
                                      int i0, int j4, int j2,
                                      ull (&m)[4][2], ull (&u)[4][2], ull (&w)[4]) {
#pragma unroll 8
    for (int kk = 0; kk < 16; kk++) {
        float4 a = *reinterpret_cast<const float4*>(A + kk * P + i0);
        const float* br = Bp + kk * 320;
        ulonglong2 bM = *reinterpret_cast<const ulonglong2*>(br + j4);
        ulonglong2 bU = *reinterpret_cast<const ulonglong2*>(br + 128 + j4);
        ull bW = *reinterpret_cast<const ull*>(br + 256 + j2);
        ull Ar[4] = {dup2(a.x), dup2(a.y), dup2(a.z), dup2(a.w)};
#pragma unroll
        for (int r = 0; r < 4; r++) {
            fma2(m[r][0], Ar[r], bM.x);
            fma2(m[r][1], Ar[r], bM.y);
            fma2(u[r][0], Ar[r], bU.x);
            fma2(u[r][1], Ar[r], bU.y);
            fma2(w[r], Ar[r], bW);
        }
    }
}

// ---- fused loop B: A=h2 chunk (K=32), B-panel row = [M2T|U2T|W3T] (160 fl/k)
__device__ __forceinline__ void gemmB(const float* __restrict__ A,
                                      const float* __restrict__ Bp,
                                      int i0, int j2, int jc,
                                      ull (&m)[4], ull (&u)[4], ull (&w)[4]) {
#pragma unroll 8
    for (int kk = 0; kk < 32; kk++) {
        float4 a = *reinterpret_cast<const float4*>(A + kk * P + i0);
        const float* br = Bp + kk * 160;
        ull bM = *reinterpret_cast<const ull*>(br + j2);
        ull bU = *reinterpret_cast<const ull*>(br + 64 + j2);
        ull bW = *reinterpret_cast<const ull*>(br + 128 + jc);
        ull Ar[4] = {dup2(a.x), dup2(a.y), dup2(a.z), dup2(a.w)};
#pragma unroll
        for (int r = 0; r < 4; r++) {
            fma2(m[r], Ar[r], bM);
            fma2(u[r], Ar[r], bU);
            fma2(w[r], Ar[r], bW);
        }
    }
}

// ---- fused loop C: A=h3 (K=32), B-panel row = [M3T|U3T] (64 fl/k)
__device__ __forceinline__ void gemmC(const float* __restrict__ A,
                                      const float* __restrict__ Bp,
                                      int i0, int jc, ull (&m)[4], ull (&u)[4]) {
#pragma unroll 8
    for (int kk = 0; kk < 32; kk++) {
        float4 a = *reinterpret_cast<const float4*>(A + kk * P + i0);
        const float* br = Bp + kk * 64;
        ull bM = *reinterpret_cast<const ull*>(br + jc);
        ull bU = *reinterpret_cast<const ull*>(br + 32 + jc);
        ull Ar[4] = {dup2(a.x), dup2(a.y), dup2(a.z), dup2(a.w)};
#pragma unroll
        for (int r = 0; r < 4; r++) {
            fma2(m[r], Ar[r], bM);
            fma2(u[r], Ar[r], bU);
        }
    }
}

// 5120-float panel staging: 5 float4 per thread
__device__ __forceinline__ void pld5(const float* __restrict__ src, int tid, float4 (&r)[5]) {
#pragma unroll
    for (int j = 0; j < 5; j++)
        r[j] = *reinterpret_cast<const float4*>(src + j * 1024 + tid * 4);
}
__device__ __forceinline__ void pst5(float* dst, int tid, const float4 (&r)[5]) {
#pragma unroll
    for (int j = 0; j < 5; j++)
        *reinterpret_cast<float4*>(dst + j * 1024 + tid * 4) = r[j];
}

// ---------------- prep kernel ----------------
__global__ void prep_all(const float* __restrict__ W1w, const float* __restrict__ W1b,
                         const float* __restrict__ U1w,
                         const float* __restrict__ W2w, const float* __restrict__ W2b,
                         const float* __restrict__ U2w,
                         const float* __restrict__ W3w, const float* __restrict__ W3b,
                         const float* __restrict__ U3w,
                         const float* __restrict__ fb3w, const float* __restrict__ fb3b,
                         const float* __restrict__ fb2w, const float* __restrict__ fb2b,
                         const float* __restrict__ fb1w, const float* __restrict__ fb1b) {
    __shared__ float row_s[784];
    __shared__ float red_s[128];
    const int bid = blockIdx.x;
    const int tid = threadIdx.x;   // 128

    if (bid < 128) {
        const int j = bid;
        for (int d = tid; d < 784; d += 128) row_s[d] = W1w[j * 784 + d];
        __syncthreads();
        {
            const int k = tid;
            float s = 0.f;
#pragma unroll 4
            for (int d = 0; d < 784; d++) s += row_s[d] * fb1w[d * 128 + k];
            g_PA[(k >> 4) * 5120 + (k & 15) * 320 + j] = -s;   // -M1T
        }
        float ps = 0.f;
        for (int d = tid; d < 784; d += 128) ps += row_s[d] * fb1b[d];
        red_s[tid] = ps;
        __syncthreads();
        for (int off = 64; off > 0; off >>= 1) {
            if (tid < off) red_s[tid] += red_s[tid + off];
            __syncthreads();
        }
        if (tid == 0) g_c1[j] = W1b[j] - red_s[0];
    } else if (bid < 192) {
        const int j = bid - 128;
        for (int d = tid; d < 128; d += 128) row_s[d] = W2w[j * 128 + d];
        __syncthreads();
        if (tid < 64) {
            const int k = tid;
            float s = 0.f;
#pragma unroll 4
            for (int d = 0; d < 128; d++) s += row_s[d] * fb2w[d * 64 + k];
            g_PB[(k >> 5) * 5120 + (k & 31) * 160 + j] = -s;   // -M2T
        }
        float ps = 0.f;
        for (int d = tid; d < 128; d += 128) ps += row_s[d] * fb2b[d];
        red_s[tid] = ps;
        __syncthreads();
        for (int off = 64; off > 0; off >>= 1) {
            if (tid < off) red_s[tid] += red_s[tid + off];
            __syncthreads();
        }
        if (tid == 0) g_c2[j] = W2b[j] - red_s[0];
    } else if (bid < 224) {
        const int j = bid - 192;
        for (int d = tid; d < 64; d += 128) row_s[d] = W3w[j * 64 + d];
        __syncthreads();
        if (tid < 32) {
            const int k = tid;
            float s = 0.f;
#pragma unroll 4
            for (int d = 0; d < 64; d++) s += row_s[d] * fb3w[d * 32 + k];
            g_PC[k * 64 + j] = -s;                              // -M3T
        }
        float ps = 0.f;
        for (int d = tid; d < 64; d += 128) ps += row_s[d] * fb3b[d];
        red_s[tid] = ps;
        __syncthreads();
        for (int off = 64; off > 0; off >>= 1) {
            if (tid < off) red_s[tid] += red_s[tid + off];
            __syncthreads();
        }
        if (tid == 0) g_c3[j] = W3b[j] - red_s[0];
    } else {
        const int idx0 = (bid - 224) * 128 + tid;
        const int stride = 32 * 128;
        for (int t = idx0; t < 784 * 128; t += stride) {          // W1T plain
            int k = t >> 7, j = t & 127;
            g_W1T[t] = W1w[j * 784 + k];
        }
        for (int t = idx0; t < 128 * 128; t += stride) {          // U1T into PA
            int k = t >> 7, j = t & 127;
            g_PA[(k >> 4) * 5120 + (k & 15) * 320 + 128 + j] = U1w[j * 128 + k];
        }
        for (int t = idx0; t < 128 * 64; t += stride) {           // W2T into PA
            int k = t >> 6, j = t & 63;
            g_PA[(k >> 4) * 5120 + (k & 15) * 320 + 256 + j] = W2w[j * 128 + k];
        }
        for (int t = idx0; t < 64 * 64; t += stride) {            // U2T into PB
            int k = t >> 6, j = t & 63;
            g_PB[(k >> 5) * 5120 + (k & 31) * 160 + 64 + j] = U2w[j * 64 + k];
        }
        for (int t = idx0; t < 64 * 32; t += stride) {            // W3T into PB
            int k = t >> 5, j = t & 31;
            g_PB[(k >> 5) * 5120 + (k & 31) * 160 + 128 + j] = W3w[j * 64 + k];
        }
        for (int t = idx0; t < 32 * 32; t += stride) {            // U3T into PC
            int k = t >> 5, j = t & 31;
            g_PC[k * 64 + 32 + j] = U3w[j * 32 + k];
        }
    }
}

// ---------------- main kernel ----------------
// smem floats (18624 = 74496 B, 3 CTAs/SM):
//   h1s[128*36]@0  h2s[64*36]@4608  h3s[32*36]@6912  (states end 8064)
//   buf0@8064(5120)  buf1@13184(5120)  sB@18304(320)
// phase-1 overlay: xck@0 [32][116]=3712, wck@3712 [112][128] (ends 18048 < sB).
// bufs filled only AFTER phase 1.
__global__ void __launch_bounds__(NTHR, 3)
pcnet_main(const float* __restrict__ x,
           const float* __restrict__ U1b, const float* __restrict__ U2b,
           const float* __restrict__ U3b,
           const float* __restrict__ clfw, const float* __restrict__ clfb,
           const int* __restrict__ steps_p,
           float* __restrict__ out) {
    extern __shared__ float sm[];
    float* h1s  = sm;
    float* h2s  = sm + 4608;
    float* h3s  = sm + 6912;
    float* buf0 = sm + 8064;
    float* buf1 = sm + 13184;
    float* sB   = sm + 18304;
    float* xck  = sm;           // overlay
    float* wck  = sm + 3712;    // overlay

    const int tid  = threadIdx.x;
    const int row0 = blockIdx.x * BT;
    float* const xwg = g_XW + (size_t)blockIdx.x * 4096;   // [128 cols][32 rows]

    const int wid  = tid >> 5, lane = tid & 31;
    const int rg   = ((wid & 1) << 2) + (lane >> 3);   // 0..7
    const int cq   = ((wid >> 1) << 3) + (lane & 7);   // 0..31
    const int i0   = rg * 4;          // 4 rows
    const int j4   = cq * 4;          // L1 cols
    const int j2   = cq * 2;          // L2 cols
    const int jc   = (cq & 15) * 2;   // L3 cols (halves redundant)

    int steps = *steps_p;
    if (steps < 0 || steps > 64) steps = 5;

    // stage biases (beyond phase-1 overlay)
    for (int t = tid; t < 320; t += NTHR) {
        float v;
        if (t < 32) v = g_c3[t];
        else if (t < 64) v = U3b[t - 32];
        else if (t < 128) v = g_c2[t - 64];
        else if (t < 192) v = U2b[t - 128];
        else v = U1b[t - 192];
        sB[t] = v;
    }

    // ---- phase 1: xw = x @ W1^T + c1 -> g_XW (column-major per tile) ----
    {
        const int p_i0 = (tid >> 4) * 2;       // 2 rows
        const int p_j4 = (tid & 15) * 4;
        ull axw[2][4] = {};
        for (int c = 0; c < 7; c++) {
            for (int idx = tid; idx < 32 * 28; idx += NTHR) {
                int r = idx / 28, k4 = idx - r * 28;
                *reinterpret_cast<float4*>(xck + r * 116 + k4 * 4) =
                    *reinterpret_cast<const float4*>(x + (size_t)(row0 + r) * 784 + c * 112 + k4 * 4);
            }
            for (int idx = tid; idx < 112 * 32; idx += NTHR) {
                int kk = idx >> 5, jj = idx & 31;
                *reinterpret_cast<float4*>(wck + kk * 128 + jj * 4) =
                    *reinterpret_cast<const float4*>(g_W1T + (size_t)(c * 112 + kk) * 128 + jj * 4);
            }
            __syncthreads();
#pragma unroll 4
            for (int kk = 0; kk < 112; kk++) {
                ulonglong2 b0 = *reinterpret_cast<const ulonglong2*>(wck + kk * 128 + p_j4);
                ulonglong2 b1 = *reinterpret_cast<const ulonglong2*>(wck + kk * 128 + 64 + p_j4);
                ull A0 = dup2(xck[(p_i0 + 0) * 116 + kk]);
                ull A1 = dup2(xck[(p_i0 + 1) * 116 + kk]);
                fma2(axw[0][0], A0, b0.x); fma2(axw[0][1], A0, b0.y);
                fma2(axw[0][2], A0, b1.x); fma2(axw[0][3], A0, b1.y);
                fma2(axw[1][0], A1, b0.x); fma2(axw[1][1], A1, b0.y);
                fma2(axw[1][2], A1, b1.x); fma2(axw[1][3], A1, b1.y);
            }
            __syncthreads();
        }
        float c1v[8];
#pragma unroll
        for (int t = 0; t < 4; t++) { c1v[t] = g_c1[p_j4 + t]; c1v[4 + t] = g_c1[64 + p_j4 + t]; }
#pragma unroll
        for (int c = 0; c < 4; c++) {
            int col = (c < 2) ? (p_j4 + 2 * c) : (60 + p_j4 + 2 * c);
            float lo0, hi0, lo1, hi1;
            up2(axw[0][c], lo0, hi0);
            up2(axw[1][c], lo1, hi1);
            float2 v0 = make_float2(lo0 + c1v[2 * c], lo1 + c1v[2 * c]);
            float2 v1 = make_float2(hi0 + c1v[2 * c + 1], hi1 + c1v[2 * c + 1]);
            *reinterpret_cast<float2*>(xwg + col * 32 + p_i0)       = v0;
            *reinterpret_cast<float2*>(xwg + (col + 1) * 32 + p_i0) = v1;
        }
    }
    __syncthreads();
    // zero states, preload first A-panel
    for (int i = tid; i < 8064; i += NTHR) sm[i] = 0.f;
    for (int idx = tid; idx < 1280; idx += NTHR)
        *reinterpret_cast<float4*>(buf0 + idx * 4) = *reinterpret_cast<const float4*>(g_PA + idx * 4);
    __syncthreads();

    float* cur = buf0;
    float* oth = buf1;

    // ---- step loop: 11 slots (8 A + 2 B + 1 C) ----
    for (int s = 0; s < steps; s++) {
        float4 pr[5];

        // ---- loop A: h1 @ {-M1T, U1T, W2T} over 8 slots (K=16 each) ----
        ull aM1[4][2] = {}, aU1[4][2] = {}, aW2[4] = {};
#pragma unroll 1
        for (int p = 0; p < 8; p++) {
            const float* nx = (p < 7) ? (g_PA + (p + 1) * 5120) : g_PB;
            pld5(nx, tid, pr);
            gemmA(h1s + 16 * p * P, cur, i0, j4, j2, aM1, aU1, aW2);
            pst5(oth, tid, pr); __syncthreads();
            float* t = cur; cur = oth; oth = t;
        }

        // ---- update h1 (all h1s reads done at slot A7 barrier) ----
#pragma unroll
        for (int cp = 0; cp < 2; cp++) {
            int col = j4 + 2 * cp;
            float ub0 = sB[192 + col], ub1 = sB[192 + col + 1];
            float4 x0 = *reinterpret_cast<const float4*>(xwg + col * 32 + i0);
            float4 y0 = *reinterpret_cast<const float4*>(xwg + (col + 1) * 32 + i0);
            float4 ha = *reinterpret_cast<float4*>(h1s + col * P + i0);
            float4 hb = *reinterpret_cast<float4*>(h1s + (col + 1) * P + i0);
#pragma unroll
            for (int r = 0; r < 4; r++) {
                float m0, m1, u0, u1;
                up2(aM1[r][cp], m0, m1); up2(aU1[r][cp], u0, u1);
                addf4(ha, r, ftanh(getf4(x0, r) + m0) + ftanh(u0 + ub0));
                addf4(hb, r, ftanh(getf4(y0, r) + m1) + ftanh(u1 + ub1));
            }
            *reinterpret_cast<float4*>(h1s + col * P + i0)       = ha;
            *reinterpret_cast<float4*>(h1s + (col + 1) * P + i0) = hb;
        }

        // ---- loop B: h2 @ {-M2T, U2T, W3T} over 2 slots (K=32 each) ----
        ull aM2[4] = {}, aU2[4] = {}, aW3[4] = {};
#pragma unroll 1
        for (int q = 0; q < 2; q++) {
            const float* nx = (q < 1) ? (g_PB + 5120) : g_PC;
            pld5(nx, tid, pr);
            gemmB(h2s + 32 * q * P, cur, i0, j2, jc, aM2, aU2, aW3);
            pst5(oth, tid, pr); __syncthreads();
            float* t = cur; cur = oth; oth = t;
        }

        // ---- loop C: h3 @ {-M3T, U3T} (1 slot; stages next step's A0) ----
        ull aM3[4] = {}, aU3[4] = {};
        {
            pld5(g_PA, tid, pr);
            gemmC(h3s, cur, i0, jc, aM3, aU3);
            pst5(oth, tid, pr); __syncthreads();
            float* t = cur; cur = oth; oth = t;
        }

        // ---- update h3 (cq<16 owns; halves redundant in compute) ----
        if (cq < 16) {
            float cc0 = sB[jc], cc1 = sB[jc + 1];
            float ub0 = sB[32 + jc], ub1 = sB[32 + jc + 1];
            float4 ha = *reinterpret_cast<float4*>(h3s + jc * P + i0);
            float4 hb = *reinterpret_cast<float4*>(h3s + (jc + 1) * P + i0);
#pragma unroll
            for (int r = 0; r < 4; r++) {
                float w0, w1, m0, m1, u0, u1;
                up2(aW3[r], w0, w1); up2(aM3[r], m0, m1); up2(aU3[r], u0, u1);
                addf4(ha, r, ftanh(w0 + m0 + cc0) + ftanh(u0 + ub0));
                addf4(hb, r, ftanh(w1 + m1 + cc1) + ftanh(u1 + ub1));
            }
            *reinterpret_cast<float4*>(h3s + jc * P + i0)       = ha;
            *reinterpret_cast<float4*>(h3s + (jc + 1) * P + i0) = hb;
        }

        // ---- update h2 ----
        {
            float cc0 = sB[64 + j2], cc1 = sB[64 + j2 + 1];
            float ub0 = sB[128 + j2], ub1 = sB[128 + j2 + 1];
            float4 ha = *reinterpret_cast<float4*>(h2s + j2 * P + i0);
            float4 hb = *reinterpret_cast<float4*>(h2s + (j2 + 1) * P + i0);
#pragma unroll
            for (int r = 0; r < 4; r++) {
                float w0, w1, m0, m1, u0, u1;
                up2(aW2[r], w0, w1); up2(aM2[r], m0, m1); up2(aU2[r], u0, u1);
                addf4(ha, r, ftanh(w0 + m0 + cc0) + ftanh(u0 + ub0));
                addf4(hb, r, ftanh(w1 + m1 + cc1) + ftanh(u1 + ub1));
            }
            *reinterpret_cast<float4*>(h2s + j2 * P + i0)       = ha;
            *reinterpret_cast<float4*>(h2s + (j2 + 1) * P + i0) = hb;
        }
        // h2s/h3s updates ordered before their next readers (loops B/C next step)
        // by the next step's A-slot barriers; h1s likewise by B/C slot barriers.
    }
    __syncthreads();

    // ---- classifier: out = h3 @ clf^T + clf_b ----
    for (int idx = tid; idx < BT * 10; idx += NTHR) {
        int r = idx / 10, cc = idx - r * 10;
        float sacc = clfb[cc];
#pragma unroll
        for (int k = 0; k < 32; k++) sacc += h3s[k * P + r] * clfw[cc * 32 + k];
        out[(size_t)(row0 + r) * 10 + cc] = sacc;
    }
}

// ---------------- launch ----------------
extern "C" void kernel_launch(void* const* d_in, const int* in_sizes, int n_in,
                              void* d_out, int out_size) {
    const float* x    = (const float*)d_in[0];
    const float* W1w  = (const float*)d_in[1];
    const float* W1b  = (const float*)d_in[2];
    const float* U1w  = (const float*)d_in[3];
    const float* U1b  = (const float*)d_in[4];
    const float* W2w  = (const float*)d_in[5];
    const float* W2b  = (const float*)d_in[6];
    const float* U2w  = (const float*)d_in[7];
    const float* U2b  = (const float*)d_in[8];
    const float* W3w  = (const float*)d_in[9];
    const float* W3b  = (const float*)d_in[10];
    const float* U3w  = (const float*)d_in[11];
    const float* U3b  = (const float*)d_in[12];
    const float* fb3w = (const float*)d_in[13];
    const float* fb3b = (const float*)d_in[14];
    const float* fb2w = (const float*)d_in[15];
    const float* fb2b = (const float*)d_in[16];
    const float* fb1w = (const float*)d_in[17];
    const float* fb1b = (const float*)d_in[18];
    const float* clfw = (const float*)d_in[19];
    const float* clfb = (const float*)d_in[20];
    const int*   stp  = (const int*)d_in[21];

    int B = in_sizes[0] / 784;
    if (B > 65536) B = 65536;   // g_XW capacity guard

    prep_all<<<256, 128>>>(W1w, W1b, U1w, W2w, W2b, U2w, W3w, W3b, U3w,
                           fb3w, fb3b, fb2w, fb2b, fb1w, fb1b);

    const int smem_bytes = 18624 * 4;   // 74496 -> 3 CTAs/SM
    cudaFuncSetAttribute(pcnet_main, cudaFuncAttributeMaxDynamicSharedMemorySize, smem_bytes);
    pcnet_main<<<B / BT, NTHR, smem_bytes>>>(x, U1b, U2b, U3b, clfw, clfb, stp, (float*)d_out);
}

// round 13
// speedup vs baseline: 1.0239x; 1.0239x over previous
#include <cuda_runtime.h>
#include <cstdint>

#define BT   128
#define P    132
#define NTHR 512
typedef unsigned long long ull;

// ---------------- persistent device scratch ----------------
__device__ __align__(16) float g_W1T[784*128];   // [k][j] (phase 1)
__device__ __align__(16) float g_L1P[32768];     // 16 pairs: [8][128] -M1T | [8][128] U1T
__device__ __align__(16) float g_W2T[128*64];
__device__ __align__(16) float g_M2T[64*64];     // negated
__device__ __align__(16) float g_U2T[64*64];
__device__ __align__(16) float g_L3P[4096];      // W3T[64*32] | -M3T[32*32] | U3T[32*32]
__device__ __align__(16) float g_c1[128];
__device__ __align__(16) float g_c2[64];
__device__ __align__(16) float g_c3[32];
__device__ __align__(16) float g_XW[65536*128];  // xw, column-major per 128-row tile

// ---------------- helpers ----------------
__device__ __forceinline__ ull dup2(float x) {
    ull r; asm("mov.b64 %0, {%1, %1};" : "=l"(r) : "f"(x)); return r;
}
__device__ __forceinline__ void up2(ull v, float &lo, float &hi) {
    asm("mov.b64 {%0, %1}, %2;" : "=f"(lo), "=f"(hi) : "l"(v));
}
__device__ __forceinline__ void fma2(ull &d, ull a, ull b) {
    asm("fma.rn.f32x2 %0, %1, %2, %0;" : "+l"(d) : "l"(a), "l"(b));
}
// tanh(x) = 1 - 2/(1+e^{2x})  via MUFU.EX2 + MUFU.RCP (~1e-6 abs err)
__device__ __forceinline__ float ftanh(float x) {
    float e, r;
    asm("ex2.approx.ftz.f32 %0, %1;" : "=f"(e) : "f"(x * 2.8853900817779268f));
    asm("rcp.approx.ftz.f32 %0, %1;" : "=f"(r) : "f"(e + 1.0f));
    return fmaf(-2.0f, r, 1.0f);
}
__device__ __forceinline__ void addf4(float4 &v, int r, float d) {
    if (r == 0) v.x += d; else if (r == 1) v.y += d;
    else if (r == 2) v.z += d; else v.w += d;
}
__device__ __forceinline__ float getf4(const float4 &v, int r) {
    return (r == 0) ? v.x : (r == 1) ? v.y : (r == 2) ? v.z : v.w;
}

// L1 paired dual GEMM, K=8 panel: Bm = -M1T rows, Bu = U1T rows (each [8][128])
__device__ __forceinline__ void gemmL1(const float* __restrict__ A,
                                       const float* __restrict__ Bm,
                                       const float* __restrict__ Bu,
                                       int i0, int j4, ull (&m)[8][2], ull (&u)[8][2]) {
#pragma unroll
    for (int k = 0; k < 8; k++) {
        float4 a0 = *reinterpret_cast<const float4*>(A + k * P + i0);
        float4 a1 = *reinterpret_cast<const float4*>(A + k * P + i0 + 4);
        ulonglong2 bm = *reinterpret_cast<const ulonglong2*>(Bm + k * 128 + j4);
        ulonglong2 bu = *reinterpret_cast<const ulonglong2*>(Bu + k * 128 + j4);
        ull Ar[8] = {dup2(a0.x), dup2(a0.y), dup2(a0.z), dup2(a0.w),
                     dup2(a1.x), dup2(a1.y), dup2(a1.z), dup2(a1.w)};
#pragma unroll
        for (int r = 0; r < 8; r++) {
            fma2(m[r][0], Ar[r], bm.x);
            fma2(m[r][1], Ar[r], bm.y);
            fma2(u[r][0], Ar[r], bu.x);
            fma2(u[r][1], Ar[r], bu.y);
        }
    }
}

// 8 rows x 2 cols (1 f32x2) single-B GEMM, B in smem
template<int K, int LDB, int UNR>
__device__ __forceinline__ void gemmR8(const float* __restrict__ A,
                                       const float* __restrict__ B,
                                       int i0, int j, ull (&acc)[8]) {
#pragma unroll UNR
    for (int k = 0; k < K; k++) {
        float4 a0 = *reinterpret_cast<const float4*>(A + k * P + i0);
        float4 a1 = *reinterpret_cast<const float4*>(A + k * P + i0 + 4);
        ull b = *reinterpret_cast<const ull*>(B + k * LDB + j);
        ull Ar[8] = {dup2(a0.x), dup2(a0.y), dup2(a0.z), dup2(a0.w),
                     dup2(a1.x), dup2(a1.y), dup2(a1.z), dup2(a1.w)};
#pragma unroll
        for (int r = 0; r < 8; r++) fma2(acc[r], Ar[r], b);
    }
}

// 4 rows x 2 cols single-B GEMM
template<int K, int LDB, int UNR>
__device__ __forceinline__ void gemmR4(const float* __restrict__ A,
                                       const float* __restrict__ B,
                                       int i0, int j, ull (&acc)[4]) {
#pragma unroll UNR
    for (int k = 0; k < K; k++) {
        float4 a = *reinterpret_cast<const float4*>(A + k * P + i0);
        ull b = *reinterpret_cast<const ull*>(B + k * LDB + j);
        ull Ar[4] = {dup2(a.x), dup2(a.y), dup2(a.z), dup2(a.w)};
#pragma unroll
        for (int r = 0; r < 4; r++) fma2(acc[r], Ar[r], b);
    }
}

// 2048-float panel staging: 1 float4 per thread (512 threads)
__device__ __forceinline__ void pld1(const float* __restrict__ src, int tid, float4 &r) {
    r = *reinterpret_cast<const float4*>(src + tid * 4);
}
__device__ __forceinline__ void pst1(float* dst, int tid, const float4 &r) {
    *reinterpret_cast<float4*>(dst + tid * 4) = r;
}

// ---------------- prep kernel (identical to the 1191us version) ----------------
__global__ void prep_all(const float* __restrict__ W1w, const float* __restrict__ W1b,
                         const float* __restrict__ U1w,
                         const float* __restrict__ W2w, const float* __restrict__ W2b,
                         const float* __restrict__ U2w,
                         const float* __restrict__ W3w, const float* __restrict__ W3b,
                         const float* __restrict__ U3w,
                         const float* __restrict__ fb3w, const float* __restrict__ fb3b,
                         const float* __restrict__ fb2w, const float* __restrict__ fb2b,
                         const float* __restrict__ fb1w, const float* __restrict__ fb1b) {
    __shared__ float row_s[784];
    __shared__ float red_s[128];
    const int bid = blockIdx.x;
    const int tid = threadIdx.x;   // 128

    if (bid < 128) {
        const int j = bid;
        for (int d = tid; d < 784; d += 128) row_s[d] = W1w[j * 784 + d];
        __syncthreads();
        {
            const int k = tid;
            float s = 0.f;
#pragma unroll 4
            for (int d = 0; d < 784; d++) s += row_s[d] * fb1w[d * 128 + k];
            g_L1P[(k >> 3) * 2048 + (k & 7) * 128 + j] = -s;   // -M1T pair layout
        }
        float ps = 0.f;
        for (int d = tid; d < 784; d += 128) ps += row_s[d] * fb1b[d];
        red_s[tid] = ps;
        __syncthreads();
        for (int off = 64; off > 0; off >>= 1) {
            if (tid < off) red_s[tid] += red_s[tid + off];
            __syncthreads();
        }
        if (tid == 0) g_c1[j] = W1b[j] - red_s[0];
    } else if (bid < 192) {
        const int j = bid - 128;
        for (int d = tid; d < 128; d += 128) row_s[d] = W2w[j * 128 + d];
        __syncthreads();
        if (tid < 64) {
            const int k = tid;
            float s = 0.f;
#pragma unroll 4
            for (int d = 0; d < 128; d++) s += row_s[d] * fb2w[d * 64 + k];
            g_M2T[k * 64 + j] = -s;
        }
        float ps = 0.f;
        for (int d = tid; d < 128; d += 128) ps += row_s[d] * fb2b[d];
        red_s[tid] = ps;
        __syncthreads();
        for (int off = 64; off > 0; off >>= 1) {
            if (tid < off) red_s[tid] += red_s[tid + off];
            __syncthreads();
        }
        if (tid == 0) g_c2[j] = W2b[j] - red_s[0];
    } else if (bid < 224) {
        const int j = bid - 192;
        for (int d = tid; d < 64; d += 128) row_s[d] = W3w[j * 64 + d];
        __syncthreads();
        if (tid < 32) {
            const int k = tid;
            float s = 0.f;
#pragma unroll 4
            for (int d = 0; d < 64; d++) s += row_s[d] * fb3w[d * 32 + k];
            g_L3P[2048 + k * 32 + j] = -s;    // -M3T
        }
        float ps = 0.f;
        for (int d = tid; d < 64; d += 128) ps += row_s[d] * fb3b[d];
        red_s[tid] = ps;
        __syncthreads();
        for (int off = 64; off > 0; off >>= 1) {
            if (tid < off) red_s[tid] += red_s[tid + off];
            __syncthreads();
        }
        if (tid == 0) g_c3[j] = W3b[j] - red_s[0];
    } else {
        const int idx0 = (bid - 224) * 128 + tid;
        const int stride = 32 * 128;
        for (int t = idx0; t < 784 * 128; t += stride) {
            int k = t >> 7, j = t & 127;
            g_W1T[t] = W1w[j * 784 + k];
        }
        for (int t = idx0; t < 128 * 128; t += stride) {          // U1T pair layout
            int k = t >> 7, j = t & 127;
            g_L1P[(k >> 3) * 2048 + 1024 + (k & 7) * 128 + j] = U1w[j * 128 + k];
        }
        for (int t = idx0; t < 128 * 64; t += stride) {
            int k = t >> 6, j = t & 63;
            g_W2T[t] = W2w[j * 128 + k];
        }
        for (int t = idx0; t < 64 * 64; t += stride) {
            int k = t >> 6, j = t & 63;
            g_U2T[t] = U2w[j * 64 + k];
        }
        for (int t = idx0; t < 64 * 32; t += stride) {            // W3T
            int k = t >> 5, j = t & 31;
            g_L3P[t] = W3w[j * 64 + k];
        }
        for (int t = idx0; t < 32 * 32; t += stride) {            // U3T
            int k = t >> 5, j = t & 31;
            g_L3P[3072 + t] = U3w[j * 32 + k];
        }
    }
}

// ---------------- main kernel ----------------
// smem floats (54464 = 217856 B, 1 CTA/SM, 16 warps):
//   h1s[128*132]@0  h2s[64*132]@16896  h3s[32*132]@25344  (states end 29568)
//   buf0@29568(2048)  buf1@31616(2048)  sB@33664(320)
//   RESIDENT: sW2@33984(8192)  sM2@42176(4096)  sU2@46272(4096)  sL3@50368(4096)
// phase-1 overlay (inside states region only): xck@0 [128][116]=14848,
//   wck@14848 [112][128]=14336 (ends 29184 < 29568).
__global__ void __launch_bounds__(NTHR, 1)
pcnet_main(const float* __restrict__ x,
           const float* __restrict__ U1b, const float* __restrict__ U2b,
           const float* __restrict__ U3b,
           const float* __restrict__ clfw, const float* __restrict__ clfb,
           const int* __restrict__ steps_p,
           float* __restrict__ out) {
    extern __shared__ float sm[];
    float* h1s  = sm;
    float* h2s  = sm + 16896;
    float* h3s  = sm + 25344;
    float* buf0 = sm + 29568;
    float* buf1 = sm + 31616;
    float* sB   = sm + 33664;
    float* sW2  = sm + 33984;
    float* sM2  = sm + 42176;
    float* sU2  = sm + 46272;
    float* sL3  = sm + 50368;
    float* xck  = sm;           // overlay
    float* wck  = sm + 14848;   // overlay

    const int tid  = threadIdx.x;
    const int row0 = blockIdx.x * BT;
    float* const xwg = g_XW + (size_t)blockIdx.x * 16384;   // [128 cols][128 rows]

    const int wid  = tid >> 5, lane = tid & 31;
    // L1/L2 mapping: warp spans 4 row-groups x 8 col-quads; 4 warp-rows x 4 warp-cols
    const int rg   = ((wid & 3) << 2) + (lane >> 3);   // 0..15
    const int cq   = ((wid >> 2) << 3) + (lane & 7);   // 0..31
    const int i0   = rg * 8;
    const int j4   = cq * 4;      // L1 cols
    const int j2   = cq * 2;      // L2 cols
    // L3 mapping: 8 warp-rows x 2 warp-cols
    const int rg3  = ((wid & 7) << 2) + (lane >> 3);   // 0..31
    const int cq3  = ((wid >> 3) << 3) + (lane & 7);   // 0..15
    const int i03  = rg3 * 4;
    const int j3   = cq3 * 2;

    int steps = *steps_p;
    if (steps < 0 || steps > 64) steps = 5;

    // stage biases + resident weights (regions beyond phase-1 overlay)
    for (int t = tid; t < 320; t += NTHR) {
        float v;
        if (t < 32) v = g_c3[t];
        else if (t < 64) v = U3b[t - 32];
        else if (t < 128) v = g_c2[t - 64];
        else if (t < 192) v = U2b[t - 128];
        else v = U1b[t - 192];
        sB[t] = v;
    }
    for (int idx = tid; idx < 2048; idx += NTHR)
        *reinterpret_cast<float4*>(sW2 + idx * 4) = *reinterpret_cast<const float4*>(g_W2T + idx * 4);
    for (int idx = tid; idx < 1024; idx += NTHR)
        *reinterpret_cast<float4*>(sM2 + idx * 4) = *reinterpret_cast<const float4*>(g_M2T + idx * 4);
    for (int idx = tid; idx < 1024; idx += NTHR)
        *reinterpret_cast<float4*>(sU2 + idx * 4) = *reinterpret_cast<const float4*>(g_U2T + idx * 4);
    for (int idx = tid; idx < 1024; idx += NTHR)
        *reinterpret_cast<float4*>(sL3 + idx * 4) = *reinterpret_cast<const float4*>(g_L3P + idx * 4);

    // ---- phase 1: xw = x @ W1^T + c1 -> g_XW (column-major per tile) ----
    {
        const int p_i0 = (tid >> 4) * 4;       // 0..124
        const int p_j4 = (tid & 15) * 4;
        ull axw[4][4] = {};
        for (int c = 0; c < 7; c++) {
            for (int idx = tid; idx < 128 * 28; idx += NTHR) {
                int r = idx / 28, k4 = idx - r * 28;
                *reinterpret_cast<float4*>(xck + r * 116 + k4 * 4) =
                    *reinterpret_cast<const float4*>(x + (size_t)(row0 + r) * 784 + c * 112 + k4 * 4);
            }
            for (int idx = tid; idx < 112 * 32; idx += NTHR) {
                int kk = idx >> 5, jj = idx & 31;
                *reinterpret_cast<float4*>(wck + kk * 128 + jj * 4) =
                    *reinterpret_cast<const float4*>(g_W1T + (size_t)(c * 112 + kk) * 128 + jj * 4);
            }
            __syncthreads();
#pragma unroll 2
            for (int kk = 0; kk < 112; kk++) {
                ulonglong2 b0 = *reinterpret_cast<const ulonglong2*>(wck + kk * 128 + p_j4);
                ulonglong2 b1 = *reinterpret_cast<const ulonglong2*>(wck + kk * 128 + 64 + p_j4);
                ull Ar[4] = {dup2(xck[(p_i0 + 0) * 116 + kk]), dup2(xck[(p_i0 + 1) * 116 + kk]),
                             dup2(xck[(p_i0 + 2) * 116 + kk]), dup2(xck[(p_i0 + 3) * 116 + kk])};
#pragma unroll
                for (int r = 0; r < 4; r++) {
                    fma2(axw[r][0], Ar[r], b0.x);
                    fma2(axw[r][1], Ar[r], b0.y);
                    fma2(axw[r][2], Ar[r], b1.x);
                    fma2(axw[r][3], Ar[r], b1.y);
                }
            }
            __syncthreads();
        }
        float c1v[8];
#pragma unroll
        for (int t = 0; t < 4; t++) { c1v[t] = g_c1[p_j4 + t]; c1v[4 + t] = g_c1[64 + p_j4 + t]; }
#pragma unroll
        for (int c = 0; c < 4; c++) {
            int col = (c < 2) ? (p_j4 + 2 * c) : (60 + p_j4 + 2 * c);
            float4 v0, v1;
#pragma unroll
            for (int r = 0; r < 4; r++) {
                float lo, hi;
                up2(axw[r][c], lo, hi);
                if (r == 0) { v0.x = lo + c1v[2 * c]; v1.x = hi + c1v[2 * c + 1]; }
                else if (r == 1) { v0.y = lo + c1v[2 * c]; v1.y = hi + c1v[2 * c + 1]; }
                else if (r == 2) { v0.z = lo + c1v[2 * c]; v1.z = hi + c1v[2 * c + 1]; }
                else { v0.w = lo + c1v[2 * c]; v1.w = hi + c1v[2 * c + 1]; }
            }
            *reinterpret_cast<float4*>(xwg + col * 128 + p_i0)       = v0;
            *reinterpret_cast<float4*>(xwg + (col + 1) * 128 + p_i0) = v1;
        }
    }
    __syncthreads();
    // zero states, preload first L1 pair panel
    for (int i = tid; i < 29568; i += NTHR) sm[i] = 0.f;
    {
        float4 v = *reinterpret_cast<const float4*>(g_L1P + tid * 4);
        *reinterpret_cast<float4*>(buf0 + tid * 4) = v;
    }
    __syncthreads();

    float* cur = buf0;
    float* oth = buf1;

    // ---- step loop: resident L2/L3 gemms + 16 L1 panel slots ----
    for (int s = 0; s < steps; s++) {
        // L2 gemms (resident weights)
        ull aW2[8] = {}, aM2[8] = {}, aU2[8] = {};
        gemmR8<128, 64, 8>(h1s, sW2, i0, j2, aW2);
        gemmR8<64, 64, 8>(h2s, sM2, i0, j2, aM2);
        gemmR8<64, 64, 8>(h2s, sU2, i0, j2, aU2);
        // L3 gemms (resident)
        ull aW3[4] = {}, aM3[4] = {}, aU3[4] = {};
        gemmR4<64, 32, 8>(h2s, sL3, i03, j3, aW3);
        gemmR4<32, 32, 8>(h3s, sL3 + 2048, i03, j3, aM3);
        gemmR4<32, 32, 8>(h3s, sL3 + 3072, i03, j3, aU3);
        __syncthreads();   // all old-state h2s/h3s reads complete

        // ---- update h3 ----
        {
            float cc0 = sB[j3], cc1 = sB[j3 + 1];
            float ub0 = sB[32 + j3], ub1 = sB[32 + j3 + 1];
            float4 h0 = *reinterpret_cast<float4*>(h3s + j3 * P + i03);
            float4 h1v = *reinterpret_cast<float4*>(h3s + (j3 + 1) * P + i03);
#pragma unroll
            for (int r = 0; r < 4; r++) {
                float w0, w1, m0, m1, u0, u1;
                up2(aW3[r], w0, w1); up2(aM3[r], m0, m1); up2(aU3[r], u0, u1);
                addf4(h0, r, ftanh(w0 + m0 + cc0) + ftanh(u0 + ub0));
                addf4(h1v, r, ftanh(w1 + m1 + cc1) + ftanh(u1 + ub1));
            }
            *reinterpret_cast<float4*>(h3s + j3 * P + i03) = h0;
            *reinterpret_cast<float4*>(h3s + (j3 + 1) * P + i03) = h1v;
        }
        // ---- update h2 ----
        {
            float cc0 = sB[64 + j2], cc1 = sB[64 + j2 + 1];
            float ub0 = sB[128 + j2], ub1 = sB[128 + j2 + 1];
            float4 ha0 = *reinterpret_cast<float4*>(h2s + j2 * P + i0);
            float4 ha1 = *reinterpret_cast<float4*>(h2s + j2 * P + i0 + 4);
            float4 hb0 = *reinterpret_cast<float4*>(h2s + (j2 + 1) * P + i0);
            float4 hb1 = *reinterpret_cast<float4*>(h2s + (j2 + 1) * P + i0 + 4);
#pragma unroll
            for (int r = 0; r < 8; r++) {
                float w0, w1, m0, m1, u0, u1;
                up2(aW2[r], w0, w1); up2(aM2[r], m0, m1); up2(aU2[r], u0, u1);
                float d0 = ftanh(w0 + m0 + cc0) + ftanh(u0 + ub0);
                float d1 = ftanh(w1 + m1 + cc1) + ftanh(u1 + ub1);
                if (r < 4) { addf4(ha0, r, d0); addf4(hb0, r, d1); }
                else       { addf4(ha1, r - 4, d0); addf4(hb1, r - 4, d1); }
            }
            *reinterpret_cast<float4*>(h2s + j2 * P + i0)           = ha0;
            *reinterpret_cast<float4*>(h2s + j2 * P + i0 + 4)       = ha1;
            *reinterpret_cast<float4*>(h2s + (j2 + 1) * P + i0)     = hb0;
            *reinterpret_cast<float4*>(h2s + (j2 + 1) * P + i0 + 4) = hb1;
        }

        // ---- L1: 16 streamed pair-panels (-M1T | U1T), K=8 each ----
        ull aM1[8][2] = {}, aU1[8][2] = {};
#pragma unroll 1
        for (int p = 0; p < 16; p++) {
            float4 pr;
            const float* nx = g_L1P + (((p + 1) & 15) * 2048);
            pld1(nx, tid, pr);
            gemmL1(h1s + 8 * p * P, cur, cur + 1024, i0, j4, aM1, aU1);
            pst1(oth, tid, pr); __syncthreads();
            float* t = cur; cur = oth; oth = t;
        }

        // ---- update h1 (xw from L2-resident g_XW, column-major) ----
#pragma unroll
        for (int cp = 0; cp < 2; cp++) {
            int col = j4 + 2 * cp;
            float ub0 = sB[192 + col], ub1 = sB[192 + col + 1];
            float4 x0 = *reinterpret_cast<const float4*>(xwg + col * 128 + i0);
            float4 x1 = *reinterpret_cast<const float4*>(xwg + col * 128 + i0 + 4);
            float4 y0 = *reinterpret_cast<const float4*>(xwg + (col + 1) * 128 + i0);
            float4 y1 = *reinterpret_cast<const float4*>(xwg + (col + 1) * 128 + i0 + 4);
            float4 ha0 = *reinterpret_cast<float4*>(h1s + col * P + i0);
            float4 ha1 = *reinterpret_cast<float4*>(h1s + col * P + i0 + 4);
            float4 hb0 = *reinterpret_cast<float4*>(h1s + (col + 1) * P + i0);
            float4 hb1 = *reinterpret_cast<float4*>(h1s + (col + 1) * P + i0 + 4);
#pragma unroll
            for (int r = 0; r < 8; r++) {
                float m0, m1, u0, u1;
                up2(aM1[r][cp], m0, m1); up2(aU1[r][cp], u0, u1);
                float xw0 = (r < 4) ? getf4(x0, r) : getf4(x1, r - 4);
                float xw1 = (r < 4) ? getf4(y0, r) : getf4(y1, r - 4);
                float d0 = ftanh(xw0 + m0) + ftanh(u0 + ub0);
                float d1 = ftanh(xw1 + m1) + ftanh(u1 + ub1);
                if (r < 4) { addf4(ha0, r, d0); addf4(hb0, r, d1); }
                else       { addf4(ha1, r - 4, d0); addf4(hb1, r - 4, d1); }
            }
            *reinterpret_cast<float4*>(h1s + col * P + i0)           = ha0;
            *reinterpret_cast<float4*>(h1s + col * P + i0 + 4)       = ha1;
            *reinterpret_cast<float4*>(h1s + (col + 1) * P + i0)     = hb0;
            *reinterpret_cast<float4*>(h1s + (col + 1) * P + i0 + 4) = hb1;
        }
        __syncthreads();   // h1/h2/h3 updates visible before next step's gemms
    }

    // ---- classifier: out = h3 @ clf^T + clf_b ----
    for (int idx = tid; idx < BT * 10; idx += NTHR) {
        int r = idx / 10, cc = idx - r * 10;
        float sacc = clfb[cc];
#pragma unroll
        for (int k = 0; k < 32; k++) sacc += h3s[k * P + r] * clfw[cc * 32 + k];
        out[(size_t)(row0 + r) * 10 + cc] = sacc;
    }
}

// ---------------- launch ----------------
extern "C" void kernel_launch(void* const* d_in, const int* in_sizes, int n_in,
                              void* d_out, int out_size) {
    const float* x    = (const float*)d_in[0];
    const float* W1w  = (const float*)d_in[1];
    const float* W1b  = (const float*)d_in[2];
    const float* U1w  = (const float*)d_in[3];
    const float* U1b  = (const float*)d_in[4];
    const float* W2w  = (const float*)d_in[5];
    const float* W2b  = (const float*)d_in[6];
    const float* U2w  = (const float*)d_in[7];
    const float* U2b  = (const float*)d_in[8];
    const float* W3w  = (const float*)d_in[9];
    const float* W3b  = (const float*)d_in[10];
    const float* U3w  = (const float*)d_in[11];
    const float* U3b  = (const float*)d_in[12];
    const float* fb3w = (const float*)d_in[13];
    const float* fb3b = (const float*)d_in[14];
    const float* fb2w = (const float*)d_in[15];
    const float* fb2b = (const float*)d_in[16];
    const float* fb1w = (const float*)d_in[17];
    const float* fb1b = (const float*)d_in[18];
    const float* clfw = (const float*)d_in[19];
    const float* clfb = (const float*)d_in[20];
    const int*   stp  = (const int*)d_in[21];

    int B = in_sizes[0] / 784;
    if (B > 65536) B = 65536;   // g_XW capacity guard

    prep_all<<<256, 128>>>(W1w, W1b, U1w, W2w, W2b, U2w, W3w, W3b, U3w,
                           fb3w, fb3b, fb2w, fb2b, fb1w, fb1b);

    const int smem_bytes = 54464 * 4;   // 217856 -> 1 CTA/SM, 16 warps
    cudaFuncSetAttribute(pcnet_main, cudaFuncAttributeMaxDynamicSharedMemorySize, smem_bytes);
    pcnet_main<<<B / BT, NTHR, smem_bytes>>>(x, U1b, U2b, U3b, clfw, clfb, stp, (float*)d_out);
}

// round 15
// speedup vs baseline: 1.3875x; 1.3551x over previous
#include <cuda_runtime.h>
#include <cuda_bf16.h>
#include <cstdint>

#define BT   64
#define P    68
#define NTHR 256
typedef unsigned long long ull;

// ---------------- persistent device scratch ----------------
__device__ __align__(16) float g_L1P[32768];     // 8 pairs: [16][128] -M1T | [16][128] U1T
__device__ __align__(16) float g_W22T[192*64];   // rows 0-127: W2T, rows 128-191: -M2T
__device__ __align__(16) float g_U2T[64*64];
__device__ __align__(16) float g_L3[4096];       // W3T[64][32] | -M3T[32][32] | U3T[32][32]
__device__ __align__(16) float g_c1[128];
__device__ __align__(16) float g_c2[64];
__device__ __align__(16) float g_c3[32];
__device__ __align__(16) float g_XW[65536*128];  // xw, column-major per 64-row tile
// W1^T split to bf16 hi/lo: [128 n][896 k] row-major (K padded 784->896 with zeros)
__device__ __align__(16) __nv_bfloat16 g_W1hT[128*896];
__device__ __align__(16) __nv_bfloat16 g_W1lT[128*896];

// ---------------- generic helpers ----------------
__device__ __forceinline__ ull dup2(float x) {
    ull r; asm("mov.b64 %0, {%1, %1};" : "=l"(r) : "f"(x)); return r;
}
__device__ __forceinline__ void up2(ull v, float &lo, float &hi) {
    asm("mov.b64 {%0, %1}, %2;" : "=f"(lo), "=f"(hi) : "l"(v));
}
__device__ __forceinline__ void fma2(ull &d, ull a, ull b) {
    asm("fma.rn.f32x2 %0, %1, %2, %0;" : "+l"(d) : "l"(a), "l"(b));
}
__device__ __forceinline__ float ftanh(float x) {
    float e, r;
    asm("ex2.approx.ftz.f32 %0, %1;" : "=f"(e) : "f"(x * 2.8853900817779268f));
    asm("rcp.approx.ftz.f32 %0, %1;" : "=f"(r) : "f"(e + 1.0f));
    return fmaf(-2.0f, r, 1.0f);
}
__device__ __forceinline__ void addf4(float4 &v, int r, float d) {
    if (r == 0) v.x += d; else if (r == 1) v.y += d;
    else if (r == 2) v.z += d; else v.w += d;
}
__device__ __forceinline__ float getf4(const float4 &v, int r) {
    return (r == 0) ? v.x : (r == 1) ? v.y : (r == 2) ? v.z : v.w;
}

// warp-level bf16 MMA (sm_80+ baseline; valid on plain sm_103)
__device__ __forceinline__ void hmma(float (&c)[4],
                                     uint32_t a0, uint32_t a1, uint32_t a2, uint32_t a3,
                                     uint32_t b0, uint32_t b1) {
    asm volatile(
        "mma.sync.aligned.m16n8k16.row.col.f32.bf16.bf16.f32 "
        "{%0,%1,%2,%3}, {%4,%5,%6,%7}, {%8,%9}, {%0,%1,%2,%3};"
        : "+f"(c[0]), "+f"(c[1]), "+f"(c[2]), "+f"(c[3])
        : "r"(a0), "r"(a1), "r"(a2), "r"(a3), "r"(b0), "r"(b1));
}

__device__ __forceinline__ uint32_t pack_bf16x2(float a, float b) {
    __nv_bfloat162 v = __floats2bfloat162_rn(a, b);
    return *reinterpret_cast<uint32_t*>(&v);
}

// ---------------- phase-1 tensor kernel (HMMA) ----------------
// Each CTA: xw[128 rows, 128 cols] = x[128, 896pad] @ W1^T, bf16 3-term split.
// smem bf16 pitch 136 per row -> conflict-free fragment loads.
// layout (bf16 elems): xh[128*136] | xl | wh[128*136] | wl, then c1s (128 f32).
#define PW 136
__global__ void __launch_bounds__(256, 1)
phase1_mma(const float* __restrict__ x) {
    extern __shared__ __nv_bfloat16 sb16[];
    __nv_bfloat16* xh = sb16;
    __nv_bfloat16* xl = xh + 128 * PW;
    __nv_bfloat16* wh = xl + 128 * PW;
    __nv_bfloat16* wl = wh + 128 * PW;
    float* c1s = reinterpret_cast<float*>(wl + 128 * PW);

    const int tid = threadIdx.x;
    const int wid = tid >> 5, lane = tid & 31;
    const int gid = lane >> 2;        // 0..7
    const int tq  = lane & 3;         // 0..3
    const int row0 = blockIdx.x * 128;

    for (int t = tid; t < 128; t += 256) c1s[t] = g_c1[t];

    float acc[16][4];
#pragma unroll
    for (int n = 0; n < 16; n++)
#pragma unroll
        for (int q = 0; q < 4; q++) acc[n][q] = 0.f;

    for (int c = 0; c < 7; c++) {
        __syncthreads();   // previous chunk's fragment reads complete
        // stage W1^T chunk: [128 n][128 k] bf16 hi/lo (source is padded with zeros)
        for (int idx = tid; idx < 4096; idx += 256) {
            int n = idx >> 5, kq = (idx & 31) * 4;
            *reinterpret_cast<uint2*>(wh + n * PW + kq) =
                *reinterpret_cast<const uint2*>(g_W1hT + n * 896 + c * 128 + kq);
            *reinterpret_cast<uint2*>(wl + n * PW + kq) =
                *reinterpret_cast<const uint2*>(g_W1lT + n * 896 + c * 128 + kq);
        }
        // stage x chunk -> bf16 hi/lo
        for (int idx = tid; idx < 4096; idx += 256) {
            int row = idx >> 5, kq = (idx & 31) * 4;
            float4 v = make_float4(0.f, 0.f, 0.f, 0.f);
            if (c < 6 || kq < 16)
                v = *reinterpret_cast<const float4*>(
                        x + (size_t)(row0 + row) * 784 + c * 128 + kq);
            float h0 = __bfloat162float(__float2bfloat16(v.x));
            float h1 = __bfloat162float(__float2bfloat16(v.y));
            float h2 = __bfloat162float(__float2bfloat16(v.z));
            float h3 = __bfloat162float(__float2bfloat16(v.w));
            uint2 ph = make_uint2(pack_bf16x2(h0, h1), pack_bf16x2(h2, h3));
            uint2 pl = make_uint2(pack_bf16x2(v.x - h0, v.y - h1),
                                  pack_bf16x2(v.z - h2, v.w - h3));
            *reinterpret_cast<uint2*>(xh + row * PW + kq) = ph;
            *reinterpret_cast<uint2*>(xl + row * PW + kq) = pl;
        }
        __syncthreads();

        const int arow = 16 * wid + gid;
#pragma unroll 2
        for (int s = 0; s < 8; s++) {
            const int k0 = s * 16;
            const __nv_bfloat16* ar = xh + arow * PW + k0 + tq * 2;
            const __nv_bfloat16* al = xl + arow * PW + k0 + tq * 2;
            uint32_t ah0 = *reinterpret_cast<const uint32_t*>(ar);
            uint32_t ah1 = *reinterpret_cast<const uint32_t*>(ar + 8 * PW);
            uint32_t ah2 = *reinterpret_cast<const uint32_t*>(ar + 8);
            uint32_t ah3 = *reinterpret_cast<const uint32_t*>(ar + 8 * PW + 8);
            uint32_t al0 = *reinterpret_cast<const uint32_t*>(al);
            uint32_t al1 = *reinterpret_cast<const uint32_t*>(al + 8 * PW);
            uint32_t al2 = *reinterpret_cast<const uint32_t*>(al + 8);
            uint32_t al3 = *reinterpret_cast<const uint32_t*>(al + 8 * PW + 8);
#pragma unroll
            for (int nt = 0; nt < 16; nt++) {
                const int colb = nt * 8 + gid;
                const __nv_bfloat16* bh = wh + colb * PW + k0 + tq * 2;
                const __nv_bfloat16* bl = wl + colb * PW + k0 + tq * 2;
                uint32_t bh0 = *reinterpret_cast<const uint32_t*>(bh);
                uint32_t bh1 = *reinterpret_cast<const uint32_t*>(bh + 8);
                uint32_t bl0 = *reinterpret_cast<const uint32_t*>(bl);
                uint32_t bl1 = *reinterpret_cast<const uint32_t*>(bl + 8);
                hmma(acc[nt], ah0, ah1, ah2, ah3, bh0, bh1);
                hmma(acc[nt], ah0, ah1, ah2, ah3, bl0, bl1);
                hmma(acc[nt], al0, al1, al2, al3, bh0, bh1);
            }
        }
    }

    // epilogue: write xw (+c1) to g_XW column-major per 64-row tile
    // thread owns rows r0 = 16*wid+gid, r1 = r0+8; cols nt*8 + tq*2 (+1)
    const int r0 = 16 * wid + gid;
    const int r1 = r0 + 8;
    const size_t ob0 = ((size_t)(blockIdx.x * 2 + (r0 >> 6))) * 8192 + (r0 & 63);
    const size_t ob1 = ((size_t)(blockIdx.x * 2 + (r1 >> 6))) * 8192 + (r1 & 63);
#pragma unroll
    for (int nt = 0; nt < 16; nt++) {
        int c0 = nt * 8 + tq * 2;
        int c1 = c0 + 1;
        g_XW[ob0 + (size_t)c0 * 64] = acc[nt][0] + c1s[c0];
        g_XW[ob0 + (size_t)c1 * 64] = acc[nt][1] + c1s[c1];
        g_XW[ob1 + (size_t)c0 * 64] = acc[nt][2] + c1s[c0];
        g_XW[ob1 + (size_t)c1 * 64] = acc[nt][3] + c1s[c1];
    }
}

// ---------------- prep kernel ----------------
__global__ void prep_all(const float* __restrict__ W1w, const float* __restrict__ W1b,
                         const float* __restrict__ U1w,
                         const float* __restrict__ W2w, const float* __restrict__ W2b,
                         const float* __restrict__ U2w,
                         const float* __restrict__ W3w, const float* __restrict__ W3b,
                         const float* __restrict__ U3w,
                         const float* __restrict__ fb3w, const float* __restrict__ fb3b,
                         const float* __restrict__ fb2w, const float* __restrict__ fb2b,
                         const float* __restrict__ fb1w, const float* __restrict__ fb1b) {
    __shared__ float row_s[784];
    __shared__ float red_s[128];
    const int bid = blockIdx.x;
    const int tid = threadIdx.x;   // 128

    if (bid < 128) {
        const int j = bid;
        for (int d = tid; d < 784; d += 128) row_s[d] = W1w[j * 784 + d];
        __syncthreads();
        {
            const int k = tid;
            float s = 0.f;
#pragma unroll 4
            for (int d = 0; d < 784; d++) s += row_s[d] * fb1w[d * 128 + k];
            g_L1P[(k >> 4) * 4096 + (k & 15) * 128 + j] = -s;   // -M1T pair layout
        }
        float ps = 0.f;
        for (int d = tid; d < 784; d += 128) ps += row_s[d] * fb1b[d];
        red_s[tid] = ps;
        __syncthreads();
        for (int off = 64; off > 0; off >>= 1) {
            if (tid < off) red_s[tid] += red_s[tid + off];
            __syncthreads();
        }
        if (tid == 0) g_c1[j] = W1b[j] - red_s[0];
    } else if (bid < 192) {
        const int j = bid - 128;
        for (int d = tid; d < 128; d += 128) row_s[d] = W2w[j * 128 + d];
        __syncthreads();
        if (tid < 64) {
            const int k = tid;
            float s = 0.f;
#pragma unroll 4
            for (int d = 0; d < 128; d++) s += row_s[d] * fb2w[d * 64 + k];
            g_W22T[(128 + k) * 64 + j] = -s;   // -M2T rows of stacked weight
        }
        float ps = 0.f;
        for (int d = tid; d < 128; d += 128) ps += row_s[d] * fb2b[d];
        red_s[tid] = ps;
        __syncthreads();
        for (int off = 64; off > 0; off >>= 1) {
            if (tid < off) red_s[tid] += red_s[tid + off];
            __syncthreads();
        }
        if (tid == 0) g_c2[j] = W2b[j] - red_s[0];
    } else if (bid < 224) {
        const int j = bid - 192;
        for (int d = tid; d < 64; d += 128) row_s[d] = W3w[j * 64 + d];
        __syncthreads();
        if (tid < 32) {
            const int k = tid;
            float s = 0.f;
#pragma unroll 4
            for (int d = 0; d < 64; d++) s += row_s[d] * fb3w[d * 32 + k];
            g_L3[(64 + k) * 32 + j] = -s;    // -M3T
        }
        float ps = 0.f;
        for (int d = tid; d < 64; d += 128) ps += row_s[d] * fb3b[d];
        red_s[tid] = ps;
        __syncthreads();
        for (int off = 64; off > 0; off >>= 1) {
            if (tid < off) red_s[tid] += red_s[tid + off];
            __syncthreads();
        }
        if (tid == 0) g_c3[j] = W3b[j] - red_s[0];
    } else {
        const int idx0 = (bid - 224) * 128 + tid;
        const int stride = 32 * 128;
        // W1^T bf16 split, [n][896] row-major, zero-padded K
        for (int t = idx0; t < 128 * 896; t += stride) {
            int n = t / 896, k = t - n * 896;
            float v = (k < 784) ? W1w[n * 784 + k] : 0.f;
            __nv_bfloat16 h = __float2bfloat16(v);
            g_W1hT[t] = h;
            g_W1lT[t] = __float2bfloat16(v - __bfloat162float(h));
        }
        for (int t = idx0; t < 128 * 128; t += stride) {          // U1T pair layout
            int k = t >> 7, j = t & 127;
            g_L1P[(k >> 4) * 4096 + 2048 + (k & 15) * 128 + j] = U1w[j * 128 + k];
        }
        for (int t = idx0; t < 128 * 64; t += stride) {           // W2T rows of stacked
            int k = t >> 6, j = t & 63;
            g_W22T[t] = W2w[j * 128 + k];
        }
        for (int t = idx0; t < 64 * 64; t += stride) {
            int k = t >> 6, j = t & 63;
            g_U2T[t] = U2w[j * 64 + k];
        }
        for (int t = idx0; t < 64 * 32; t += stride) {            // W3T
            int k = t >> 5, j = t & 31;
            g_L3[t] = W3w[j * 64 + k];
        }
        for (int t = idx0; t < 32 * 32; t += stride) {            // U3T
            int k = t >> 5, j = t & 31;
            g_L3[3072 + t] = U3w[j * 32 + k];
        }
    }
}

// ---------------- main-loop GEMM helpers (R8-proven) ----------------
__device__ __forceinline__ void gemmL1(const float* __restrict__ A,
                                       const float* __restrict__ Bm,
                                       const float* __restrict__ Bu,
                                       int i0, int j4, ull (&m)[8][2], ull (&u)[8][2]) {
#pragma unroll
    for (int k = 0; k < 16; k++) {
        float4 a0 = *reinterpret_cast<const float4*>(A + k * P + i0);
        float4 a1 = *reinterpret_cast<const float4*>(A + k * P + i0 + 4);
        ulonglong2 bm = *reinterpret_cast<const ulonglong2*>(Bm + k * 128 + j4);
        ulonglong2 bu = *reinterpret_cast<const ulonglong2*>(Bu + k * 128 + j4);
        ull Ar[8] = {dup2(a0.x), dup2(a0.y), dup2(a0.z), dup2(a0.w),
                     dup2(a1.x), dup2(a1.y), dup2(a1.z), dup2(a1.w)};
#pragma unroll
        for (int r = 0; r < 8; r++) {
            fma2(m[r][0], Ar[r], bm.x);
            fma2(m[r][1], Ar[r], bm.y);
            fma2(u[r][0], Ar[r], bu.x);
            fma2(u[r][1], Ar[r], bu.y);
        }
    }
}
template<int K, int LDB, int UNR>
__device__ __forceinline__ void gemmR8(const float* __restrict__ A,
                                       const float* __restrict__ B,
                                       int i0, int j, ull (&acc)[8]) {
#pragma unroll UNR
    for (int k = 0; k < K; k++) {
        float4 a0 = *reinterpret_cast<const float4*>(A + k * P + i0);
        float4 a1 = *reinterpret_cast<const float4*>(A + k * P + i0 + 4);
        ull b = *reinterpret_cast<const ull*>(B + k * LDB + j);
        ull Ar[8] = {dup2(a0.x), dup2(a0.y), dup2(a0.z), dup2(a0.w),
                     dup2(a1.x), dup2(a1.y), dup2(a1.z), dup2(a1.w)};
#pragma unroll
        for (int r = 0; r < 8; r++) fma2(acc[r], Ar[r], b);
    }
}
template<int K, int LDB, int UNR>
__device__ __forceinline__ void gemmR4(const float* __restrict__ A,
                                       const float* __restrict__ B,
                                       int i0, int j, ull (&acc)[4]) {
#pragma unroll UNR
    for (int k = 0; k < K; k++) {
        float4 a = *reinterpret_cast<const float4*>(A + k * P + i0);
        ull b = *reinterpret_cast<const ull*>(B + k * LDB + j);
        ull Ar[4] = {dup2(a.x), dup2(a.y), dup2(a.z), dup2(a.w)};
#pragma unroll
        for (int r = 0; r < 4; r++) fma2(acc[r], Ar[r], b);
    }
}
__device__ __forceinline__ void pld4(const float* __restrict__ src, int tid, float4 (&r)[4]) {
#pragma unroll
    for (int j = 0; j < 4; j++)
        r[j] = *reinterpret_cast<const float4*>(src + j * 1024 + tid * 4);
}
__device__ __forceinline__ void pst4(float* dst, int tid, const float4 (&r)[4]) {
#pragma unroll
    for (int j = 0; j < 4; j++)
        *reinterpret_cast<float4*>(dst + j * 1024 + tid * 4) = r[j];
}

// ---------------- main kernel (R8 proven loop; xw from g_XW) ----------------
// smem floats (23744 = 94976 B, 2 CTAs/SM):
//   h1s[128*68]@0  h2s[64*68]@8704  h3s[32*68]@13056
//   buf0@15232(4096)  buf1@19328(4096)  sB@23424(320)
__global__ void __launch_bounds__(NTHR, 2)
pcnet_main(const float* __restrict__ U1b, const float* __restrict__ U2b,
           const float* __restrict__ U3b,
           const float* __restrict__ clfw, const float* __restrict__ clfb,
           const int* __restrict__ steps_p,
           float* __restrict__ out) {
    extern __shared__ float sm[];
    float* h1s  = sm;
    float* h2s  = sm + 8704;
    float* h3s  = sm + 13056;
    float* buf0 = sm + 15232;
    float* buf1 = sm + 19328;
    float* sB   = sm + 23424;

    const int tid  = threadIdx.x;
    const int row0 = blockIdx.x * BT;
    const float* const xwg = g_XW + (size_t)blockIdx.x * 8192;   // [128 cols][64 rows]

    const int wid  = tid >> 5, lane = tid & 31;
    const int rg   = ((wid & 1) << 2) + (lane >> 3);   // 0..7
    const int cq   = ((wid >> 1) << 3) + (lane & 7);   // 0..31
    const int i0   = rg * 8;
    const int j4   = cq * 4;      // L1 cols
    const int j2   = cq * 2;      // L2 cols
    const int rg3  = ((wid & 3) << 2) + (lane >> 3);   // 0..15
    const int cq3  = ((wid >> 2) << 3) + (lane & 7);   // 0..15
    const int i03  = rg3 * 4;
    const int j3   = cq3 * 2;

    int steps = *steps_p;
    if (steps < 0 || steps > 64) steps = 5;

    // biases + zero states + first panel
    for (int t = tid; t < 320; t += NTHR) {
        float v;
        if (t < 32) v = g_c3[t];
        else if (t < 64) v = U3b[t - 32];
        else if (t < 128) v = g_c2[t - 64];
        else if (t < 192) v = U2b[t - 128];
        else v = U1b[t - 192];
        sB[t] = v;
    }
    for (int i = tid; i < 15232; i += NTHR) sm[i] = 0.f;
    for (int idx = tid; idx < 1024; idx += NTHR)
        *reinterpret_cast<float4*>(buf0 + idx * 4) = *reinterpret_cast<const float4*>(g_L3 + idx * 4);
    __syncthreads();

    float* cur = buf0;
    float* oth = buf1;

    // ---- step loop: 13 panel slots ----
    for (int s = 0; s < steps; s++) {
        float4 pr[4];

        // slot 0: L3 full panel (W3T | -M3T | U3T)
        ull aA3[4] = {}, aU3[4] = {};
        pld4(g_W22T, tid, pr);
        gemmR4<64, 32, 8>(h2s, cur, i03, j3, aA3);
        gemmR4<32, 32, 8>(h3s, cur + 2048, i03, j3, aA3);
        gemmR4<32, 32, 8>(h3s, cur + 3072, i03, j3, aU3);
        pst4(oth, tid, pr); __syncthreads();
        { float* t = cur; cur = oth; oth = t; }

        // ---- update h3 ----
        {
            float cc0 = sB[j3], cc1 = sB[j3 + 1];
            float ub0 = sB[32 + j3], ub1 = sB[32 + j3 + 1];
            float4 h0 = *reinterpret_cast<float4*>(h3s + j3 * P + i03);
            float4 h1v = *reinterpret_cast<float4*>(h3s + (j3 + 1) * P + i03);
#pragma unroll
            for (int r = 0; r < 4; r++) {
                float a0, a1, u0, u1;
                up2(aA3[r], a0, a1); up2(aU3[r], u0, u1);
                addf4(h0, r, ftanh(a0 + cc0) + ftanh(u0 + ub0));
                addf4(h1v, r, ftanh(a1 + cc1) + ftanh(u1 + ub1));
            }
            *reinterpret_cast<float4*>(h3s + j3 * P + i03) = h0;
            *reinterpret_cast<float4*>(h3s + (j3 + 1) * P + i03) = h1v;
        }

        // slots 1-3: concat [h1;h2] @ [W2T;-M2T], K=64 per slot
        ull aA2[8] = {};
#pragma unroll
        for (int p = 0; p < 3; p++) {
            const float* Ap = (p == 0) ? h1s : (p == 1) ? (h1s + 64 * P) : h2s;
            const float* nx = (p < 2) ? (g_W22T + (p + 1) * 4096) : g_U2T;
            pld4(nx, tid, pr);
            gemmR8<64, 64, 8>(Ap, cur, i0, j2, aA2);
            pst4(oth, tid, pr); __syncthreads();
            float* t = cur; cur = oth; oth = t;
        }
        // slot 4: U2T (K=64)
        ull aU2[8] = {};
        pld4(g_L1P, tid, pr);
        gemmR8<64, 64, 8>(h2s, cur, i0, j2, aU2);
        pst4(oth, tid, pr); __syncthreads();
        { float* t = cur; cur = oth; oth = t; }

        // ---- update h2 ----
        {
            float cc0 = sB[64 + j2], cc1 = sB[64 + j2 + 1];
            float ub0 = sB[128 + j2], ub1 = sB[128 + j2 + 1];
            float4 ha0 = *reinterpret_cast<float4*>(h2s + j2 * P + i0);
            float4 ha1 = *reinterpret_cast<float4*>(h2s + j2 * P + i0 + 4);
            float4 hb0 = *reinterpret_cast<float4*>(h2s + (j2 + 1) * P + i0);
            float4 hb1 = *reinterpret_cast<float4*>(h2s + (j2 + 1) * P + i0 + 4);
#pragma unroll
            for (int r = 0; r < 8; r++) {
                float a0, a1, u0, u1;
                up2(aA2[r], a0, a1); up2(aU2[r], u0, u1);
                float d0 = ftanh(a0 + cc0) + ftanh(u0 + ub0);
                float d1 = ftanh(a1 + cc1) + ftanh(u1 + ub1);
                if (r < 4) { addf4(ha0, r, d0); addf4(hb0, r, d1); }
                else       { addf4(ha1, r - 4, d0); addf4(hb1, r - 4, d1); }
            }
            *reinterpret_cast<float4*>(h2s + j2 * P + i0)           = ha0;
            *reinterpret_cast<float4*>(h2s + j2 * P + i0 + 4)       = ha1;
            *reinterpret_cast<float4*>(h2s + (j2 + 1) * P + i0)     = hb0;
            *reinterpret_cast<float4*>(h2s + (j2 + 1) * P + i0 + 4) = hb1;
        }

        // slots 5-12: L1 paired panels (-M1T | U1T), K=16 each
        ull aM1[8][2] = {}, aU1[8][2] = {};
#pragma unroll 1
        for (int p = 0; p < 8; p++) {
            const float* nx = (p < 7) ? (g_L1P + (p + 1) * 4096) : g_L3;
            pld4(nx, tid, pr);
            gemmL1(h1s + 16 * p * P, cur, cur + 2048, i0, j4, aM1, aU1);
            pst4(oth, tid, pr); __syncthreads();
            float* t = cur; cur = oth; oth = t;
        }

        // ---- update h1 (xw streamed from L2-resident g_XW) ----
#pragma unroll
        for (int cp = 0; cp < 2; cp++) {
            int col = j4 + 2 * cp;
            float ub0 = sB[192 + col], ub1 = sB[192 + col + 1];
            float4 xa0 = *reinterpret_cast<const float4*>(xwg + col * 64 + i0);
            float4 xa1 = *reinterpret_cast<const float4*>(xwg + col * 64 + i0 + 4);
            float4 xb0 = *reinterpret_cast<const float4*>(xwg + (col + 1) * 64 + i0);
            float4 xb1 = *reinterpret_cast<const float4*>(xwg + (col + 1) * 64 + i0 + 4);
            float4 ha0 = *reinterpret_cast<float4*>(h1s + col * P + i0);
            float4 ha1 = *reinterpret_cast<float4*>(h1s + col * P + i0 + 4);
            float4 hb0 = *reinterpret_cast<float4*>(h1s + (col + 1) * P + i0);
            float4 hb1 = *reinterpret_cast<float4*>(h1s + (col + 1) * P + i0 + 4);
#pragma unroll
            for (int r = 0; r < 8; r++) {
                float m0, m1, u0, u1;
                up2(aM1[r][cp], m0, m1); up2(aU1[r][cp], u0, u1);
                float xw0 = (r < 4) ? getf4(xa0, r) : getf4(xa1, r - 4);
                float xw1 = (r < 4) ? getf4(xb0, r) : getf4(xb1, r - 4);
                float d0 = ftanh(xw0 + m0) + ftanh(u0 + ub0);
                float d1 = ftanh(xw1 + m1) + ftanh(u1 + ub1);
                if (r < 4) { addf4(ha0, r, d0); addf4(hb0, r, d1); }
                else       { addf4(ha1, r - 4, d0); addf4(hb1, r - 4, d1); }
            }
            *reinterpret_cast<float4*>(h1s + col * P + i0)           = ha0;
            *reinterpret_cast<float4*>(h1s + col * P + i0 + 4)       = ha1;
            *reinterpret_cast<float4*>(h1s + (col + 1) * P + i0)     = hb0;
            *reinterpret_cast<float4*>(h1s + (col + 1) * P + i0 + 4) = hb1;
        }
        // h1 writes ordered before next step's first h1s read (slot 1) by the
        // next step's slot-0 barrier; h2/h3 writes covered likewise.
    }
    __syncthreads();

    // ---- classifier: out = h3 @ clf^T + clf_b ----
    for (int idx = tid; idx < BT * 10; idx += NTHR) {
        int r = idx / 10, cc = idx - r * 10;
        float sacc = clfb[cc];
#pragma unroll
        for (int k = 0; k < 32; k++) sacc += h3s[k * P + r] * clfw[cc * 32 + k];
        out[(size_t)(row0 + r) * 10 + cc] = sacc;
    }
}

// ---------------- launch ----------------
extern "C" void kernel_launch(void* const* d_in, const int* in_sizes, int n_in,
                              void* d_out, int out_size) {
    const float* x    = (const float*)d_in[0];
    const float* W1w  = (const float*)d_in[1];
    const float* W1b  = (const float*)d_in[2];
    const float* U1w  = (const float*)d_in[3];
    const float* U1b  = (const float*)d_in[4];
    const float* W2w  = (const float*)d_in[5];
    const float* W2b  = (const float*)d_in[6];
    const float* U2w  = (const float*)d_in[7];
    const float* U2b  = (const float*)d_in[8];
    const float* W3w  = (const float*)d_in[9];
    const float* W3b  = (const float*)d_in[10];
    const float* U3w  = (const float*)d_in[11];
    const float* U3b  = (const float*)d_in[12];
    const float* fb3w = (const float*)d_in[13];
    const float* fb3b = (const float*)d_in[14];
    const float* fb2w = (const float*)d_in[15];
    const float* fb2b = (const float*)d_in[16];
    const float* fb1w = (const float*)d_in[17];
    const float* fb1b = (const float*)d_in[18];
    const float* clfw = (const float*)d_in[19];
    const float* clfb = (const float*)d_in[20];
    const int*   stp  = (const int*)d_in[21];

    int B = in_sizes[0] / 784;
    if (B > 65536) B = 65536;   // g_XW capacity guard

    prep_all<<<256, 128>>>(W1w, W1b, U1w, W2w, W2b, U2w, W3w, W3b, U3w,
                           fb3w, fb3b, fb2w, fb2b, fb1w, fb1b);

    const int p1_smem = 4 * 128 * PW * 2 + 512;   // 139776 B
    cudaFuncSetAttribute(phase1_mma, cudaFuncAttributeMaxDynamicSharedMemorySize, p1_smem);
    phase1_mma<<<B / 128, 256, p1_smem>>>(x);

    const int smem_bytes = 23744 * 4;   // 94976 -> 2 CTAs/SM
    cudaFuncSetAttribute(pcnet_main, cudaFuncAttributeMaxDynamicSharedMemorySize, smem_bytes);
    pcnet_main<<<B / BT, NTHR, smem_bytes>>>(U1b, U2b, U3b, clfw, clfb, stp, (float*)d_out);
}

// round 16
// speedup vs baseline: 1.4359x; 1.0349x over previous
#include <cuda_runtime.h>
#include <cuda_bf16.h>
#include <cstdint>

#define BT   64
#define P    68
#define NTHR 256
typedef unsigned long long ull;

// ---------------- persistent device scratch ----------------
__device__ __align__(16) float g_L1P[32768];     // 8 pairs: [16][128] -M1T | [16][128] U1T
__device__ __align__(16) float g_W22T[192*64];   // rows 0-127: W2T, rows 128-191: -M2T
__device__ __align__(16) float g_U2T[64*64];
__device__ __align__(16) float g_L3[4096];       // W3T[64][32] | -M3T[32][32] | U3T[32][32]
__device__ __align__(16) float g_c1[128];
__device__ __align__(16) float g_c2[64];
__device__ __align__(16) float g_c3[32];
__device__ __align__(16) float g_XW[65536*128];  // xw, column-major per 64-row tile
// W1^T split to bf16 hi/lo: [128 n][896 k] row-major (K padded 784->896 with zeros)
__device__ __align__(16) __nv_bfloat16 g_W1hT[128*896];
__device__ __align__(16) __nv_bfloat16 g_W1lT[128*896];

// ---------------- generic helpers ----------------
__device__ __forceinline__ ull dup2(float x) {
    ull r; asm("mov.b64 %0, {%1, %1};" : "=l"(r) : "f"(x)); return r;
}
__device__ __forceinline__ void up2(ull v, float &lo, float &hi) {
    asm("mov.b64 {%0, %1}, %2;" : "=f"(lo), "=f"(hi) : "l"(v));
}
__device__ __forceinline__ void fma2(ull &d, ull a, ull b) {
    asm("fma.rn.f32x2 %0, %1, %2, %0;" : "+l"(d) : "l"(a), "l"(b));
}
__device__ __forceinline__ float ftanh(float x) {
    float e, r;
    asm("ex2.approx.ftz.f32 %0, %1;" : "=f"(e) : "f"(x * 2.8853900817779268f));
    asm("rcp.approx.ftz.f32 %0, %1;" : "=f"(r) : "f"(e + 1.0f));
    return fmaf(-2.0f, r, 1.0f);
}
__device__ __forceinline__ void addf4(float4 &v, int r, float d) {
    if (r == 0) v.x += d; else if (r == 1) v.y += d;
    else if (r == 2) v.z += d; else v.w += d;
}
__device__ __forceinline__ float getf4(const float4 &v, int r) {
    return (r == 0) ? v.x : (r == 1) ? v.y : (r == 2) ? v.z : v.w;
}

// warp-level bf16 MMA (sm_80+ baseline; valid on plain sm_103)
__device__ __forceinline__ void hmma(float (&c)[4],
                                     uint32_t a0, uint32_t a1, uint32_t a2, uint32_t a3,
                                     uint32_t b0, uint32_t b1) {
    asm volatile(
        "mma.sync.aligned.m16n8k16.row.col.f32.bf16.bf16.f32 "
        "{%0,%1,%2,%3}, {%4,%5,%6,%7}, {%8,%9}, {%0,%1,%2,%3};"
        : "+f"(c[0]), "+f"(c[1]), "+f"(c[2]), "+f"(c[3])
        : "r"(a0), "r"(a1), "r"(a2), "r"(a3), "r"(b0), "r"(b1));
}

__device__ __forceinline__ uint32_t pack_bf16x2(float a, float b) {
    __nv_bfloat162 v = __floats2bfloat162_rn(a, b);
    return *reinterpret_cast<uint32_t*>(&v);
}

// ---------------- phase-1 tensor kernel (HMMA) ----------------
// Each CTA: xw[128 rows, 128 cols] = x[128, 896pad] @ W1^T, bf16 3-term split.
#define PW 136
__global__ void __launch_bounds__(256, 1)
phase1_mma(const float* __restrict__ x) {
    extern __shared__ __nv_bfloat16 sb16[];
    __nv_bfloat16* xh = sb16;
    __nv_bfloat16* xl = xh + 128 * PW;
    __nv_bfloat16* wh = xl + 128 * PW;
    __nv_bfloat16* wl = wh + 128 * PW;
    float* c1s = reinterpret_cast<float*>(wl + 128 * PW);

    const int tid = threadIdx.x;
    const int wid = tid >> 5, lane = tid & 31;
    const int gid = lane >> 2;        // 0..7
    const int tq  = lane & 3;         // 0..3
    const int row0 = blockIdx.x * 128;

    for (int t = tid; t < 128; t += 256) c1s[t] = g_c1[t];

    float acc[16][4];
#pragma unroll
    for (int n = 0; n < 16; n++)
#pragma unroll
        for (int q = 0; q < 4; q++) acc[n][q] = 0.f;

    for (int c = 0; c < 7; c++) {
        __syncthreads();   // previous chunk's fragment reads complete
        for (int idx = tid; idx < 4096; idx += 256) {
            int n = idx >> 5, kq = (idx & 31) * 4;
            *reinterpret_cast<uint2*>(wh + n * PW + kq) =
                *reinterpret_cast<const uint2*>(g_W1hT + n * 896 + c * 128 + kq);
            *reinterpret_cast<uint2*>(wl + n * PW + kq) =
                *reinterpret_cast<const uint2*>(g_W1lT + n * 896 + c * 128 + kq);
        }
        for (int idx = tid; idx < 4096; idx += 256) {
            int row = idx >> 5, kq = (idx & 31) * 4;
            float4 v = make_float4(0.f, 0.f, 0.f, 0.f);
            if (c < 6 || kq < 16)
                v = *reinterpret_cast<const float4*>(
                        x + (size_t)(row0 + row) * 784 + c * 128 + kq);
            float h0 = __bfloat162float(__float2bfloat16(v.x));
            float h1 = __bfloat162float(__float2bfloat16(v.y));
            float h2 = __bfloat162float(__float2bfloat16(v.z));
            float h3 = __bfloat162float(__float2bfloat16(v.w));
            uint2 ph = make_uint2(pack_bf16x2(h0, h1), pack_bf16x2(h2, h3));
            uint2 pl = make_uint2(pack_bf16x2(v.x - h0, v.y - h1),
                                  pack_bf16x2(v.z - h2, v.w - h3));
            *reinterpret_cast<uint2*>(xh + row * PW + kq) = ph;
            *reinterpret_cast<uint2*>(xl + row * PW + kq) = pl;
        }
        __syncthreads();

        const int arow = 16 * wid + gid;
#pragma unroll 2
        for (int s = 0; s < 8; s++) {
            const int k0 = s * 16;
            const __nv_bfloat16* ar = xh + arow * PW + k0 + tq * 2;
            const __nv_bfloat16* al = xl + arow * PW + k0 + tq * 2;
            uint32_t ah0 = *reinterpret_cast<const uint32_t*>(ar);
            uint32_t ah1 = *reinterpret_cast<const uint32_t*>(ar + 8 * PW);
            uint32_t ah2 = *reinterpret_cast<const uint32_t*>(ar + 8);
            uint32_t ah3 = *reinterpret_cast<const uint32_t*>(ar + 8 * PW + 8);
            uint32_t al0 = *reinterpret_cast<const uint32_t*>(al);
            uint32_t al1 = *reinterpret_cast<const uint32_t*>(al + 8 * PW);
            uint32_t al2 = *reinterpret_cast<const uint32_t*>(al + 8);
            uint32_t al3 = *reinterpret_cast<const uint32_t*>(al + 8 * PW + 8);
#pragma unroll
            for (int nt = 0; nt < 16; nt++) {
                const int colb = nt * 8 + gid;
                const __nv_bfloat16* bh = wh + colb * PW + k0 + tq * 2;
                const __nv_bfloat16* bl = wl + colb * PW + k0 + tq * 2;
                uint32_t bh0 = *reinterpret_cast<const uint32_t*>(bh);
                uint32_t bh1 = *reinterpret_cast<const uint32_t*>(bh + 8);
                uint32_t bl0 = *reinterpret_cast<const uint32_t*>(bl);
                uint32_t bl1 = *reinterpret_cast<const uint32_t*>(bl + 8);
                hmma(acc[nt], ah0, ah1, ah2, ah3, bh0, bh1);
                hmma(acc[nt], ah0, ah1, ah2, ah3, bl0, bl1);
                hmma(acc[nt], al0, al1, al2, al3, bh0, bh1);
            }
        }
    }

    const int r0 = 16 * wid + gid;
    const int r1 = r0 + 8;
    const size_t ob0 = ((size_t)(blockIdx.x * 2 + (r0 >> 6))) * 8192 + (r0 & 63);
    const size_t ob1 = ((size_t)(blockIdx.x * 2 + (r1 >> 6))) * 8192 + (r1 & 63);
#pragma unroll
    for (int nt = 0; nt < 16; nt++) {
        int c0 = nt * 8 + tq * 2;
        int c1 = c0 + 1;
        g_XW[ob0 + (size_t)c0 * 64] = acc[nt][0] + c1s[c0];
        g_XW[ob0 + (size_t)c1 * 64] = acc[nt][1] + c1s[c1];
        g_XW[ob1 + (size_t)c0 * 64] = acc[nt][2] + c1s[c0];
        g_XW[ob1 + (size_t)c1 * 64] = acc[nt][3] + c1s[c1];
    }
}

// ---------------- prep kernel (multi-accumulator ILP dots) ----------------
__global__ void prep_all(const float* __restrict__ W1w, const float* __restrict__ W1b,
                         const float* __restrict__ U1w,
                         const float* __restrict__ W2w, const float* __restrict__ W2b,
                         const float* __restrict__ U2w,
                         const float* __restrict__ W3w, const float* __restrict__ W3b,
                         const float* __restrict__ U3w,
                         const float* __restrict__ fb3w, const float* __restrict__ fb3b,
                         const float* __restrict__ fb2w, const float* __restrict__ fb2b,
                         const float* __restrict__ fb1w, const float* __restrict__ fb1b) {
    __shared__ float row_s[784];
    __shared__ float red_s[128];
    const int bid = blockIdx.x;
    const int tid = threadIdx.x;   // 128

    if (bid < 128) {
        const int j = bid;
        for (int d = tid; d < 784; d += 128) row_s[d] = W1w[j * 784 + d];
        __syncthreads();
        {
            const int k = tid;
            float s0 = 0.f, s1 = 0.f, s2 = 0.f, s3 = 0.f;
            float s4 = 0.f, s5 = 0.f, s6 = 0.f, s7 = 0.f;
            for (int d = 0; d < 784; d += 8) {   // 784 = 8*98
                s0 += row_s[d + 0] * fb1w[(d + 0) * 128 + k];
                s1 += row_s[d + 1] * fb1w[(d + 1) * 128 + k];
                s2 += row_s[d + 2] * fb1w[(d + 2) * 128 + k];
                s3 += row_s[d + 3] * fb1w[(d + 3) * 128 + k];
                s4 += row_s[d + 4] * fb1w[(d + 4) * 128 + k];
                s5 += row_s[d + 5] * fb1w[(d + 5) * 128 + k];
                s6 += row_s[d + 6] * fb1w[(d + 6) * 128 + k];
                s7 += row_s[d + 7] * fb1w[(d + 7) * 128 + k];
            }
            float s = ((s0 + s1) + (s2 + s3)) + ((s4 + s5) + (s6 + s7));
            g_L1P[(k >> 4) * 4096 + (k & 15) * 128 + j] = -s;   // -M1T pair layout
        }
        // c1[j] = W1b[j] - dot(row, fb1b)   (128 parallel partials, 4-way ILP)
        float p0 = 0.f, p1 = 0.f, p2 = 0.f, p3 = 0.f;
        for (int d = tid; d < 784; d += 512) {
            p0 += row_s[d] * fb1b[d];
            if (d + 128 < 784) p1 += row_s[d + 128] * fb1b[d + 128];
            if (d + 256 < 784) p2 += row_s[d + 256] * fb1b[d + 256];
            if (d + 384 < 784) p3 += row_s[d + 384] * fb1b[d + 384];
        }
        red_s[tid] = (p0 + p1) + (p2 + p3);
        __syncthreads();
        for (int off = 64; off > 0; off >>= 1) {
            if (tid < off) red_s[tid] += red_s[tid + off];
            __syncthreads();
        }
        if (tid == 0) g_c1[j] = W1b[j] - red_s[0];
    } else if (bid < 192) {
        const int j = bid - 128;
        for (int d = tid; d < 128; d += 128) row_s[d] = W2w[j * 128 + d];
        __syncthreads();
        if (tid < 64) {
            const int k = tid;
            float s0 = 0.f, s1 = 0.f, s2 = 0.f, s3 = 0.f;
            for (int d = 0; d < 128; d += 4) {
                s0 += row_s[d + 0] * fb2w[(d + 0) * 64 + k];
                s1 += row_s[d + 1] * fb2w[(d + 1) * 64 + k];
                s2 += row_s[d + 2] * fb2w[(d + 2) * 64 + k];
                s3 += row_s[d + 3] * fb2w[(d + 3) * 64 + k];
            }
            g_W22T[(128 + k) * 64 + j] = -((s0 + s1) + (s2 + s3));   // -M2T
        }
        float ps = 0.f;
        for (int d = tid; d < 128; d += 128) ps += row_s[d] * fb2b[d];
        red_s[tid] = ps;
        __syncthreads();
        for (int off = 64; off > 0; off >>= 1) {
            if (tid < off) red_s[tid] += red_s[tid + off];
            __syncthreads();
        }
        if (tid == 0) g_c2[j] = W2b[j] - red_s[0];
    } else if (bid < 224) {
        const int j = bid - 192;
        for (int d = tid; d < 64; d += 128) row_s[d] = W3w[j * 64 + d];
        __syncthreads();
        if (tid < 32) {
            const int k = tid;
            float s0 = 0.f, s1 = 0.f, s2 = 0.f, s3 = 0.f;
            for (int d = 0; d < 64; d += 4) {
                s0 += row_s[d + 0] * fb3w[(d + 0) * 32 + k];
                s1 += row_s[d + 1] * fb3w[(d + 1) * 32 + k];
                s2 += row_s[d + 2] * fb3w[(d + 2) * 32 + k];
                s3 += row_s[d + 3] * fb3w[(d + 3) * 32 + k];
            }
            g_L3[(64 + k) * 32 + j] = -((s0 + s1) + (s2 + s3));   // -M3T
        }
        float ps = 0.f;
        for (int d = tid; d < 64; d += 128) ps += row_s[d] * fb3b[d];
        red_s[tid] = ps;
        __syncthreads();
        for (int off = 64; off > 0; off >>= 1) {
            if (tid < off) red_s[tid] += red_s[tid + off];
            __syncthreads();
        }
        if (tid == 0) g_c3[j] = W3b[j] - red_s[0];
    } else {
        const int idx0 = (bid - 224) * 128 + tid;
        const int stride = 32 * 128;
        // W1^T bf16 split, [n][896] row-major, zero-padded K
        for (int t = idx0; t < 128 * 896; t += stride) {
            int n = t / 896, k = t - n * 896;
            float v = (k < 784) ? W1w[n * 784 + k] : 0.f;
            __nv_bfloat16 h = __float2bfloat16(v);
            g_W1hT[t] = h;
            g_W1lT[t] = __float2bfloat16(v - __bfloat162float(h));
        }
        for (int t = idx0; t < 128 * 128; t += stride) {          // U1T pair layout
            int k = t >> 7, j = t & 127;
            g_L1P[(k >> 4) * 4096 + 2048 + (k & 15) * 128 + j] = U1w[j * 128 + k];
        }
        for (int t = idx0; t < 128 * 64; t += stride) {           // W2T rows of stacked
            int k = t >> 6, j = t & 63;
            g_W22T[t] = W2w[j * 128 + k];
        }
        for (int t = idx0; t < 64 * 64; t += stride) {
            int k = t >> 6, j = t & 63;
            g_U2T[t] = U2w[j * 64 + k];
        }
        for (int t = idx0; t < 64 * 32; t += stride) {            // W3T
            int k = t >> 5, j = t & 31;
            g_L3[t] = W3w[j * 64 + k];
        }
        for (int t = idx0; t < 32 * 32; t += stride) {            // U3T
            int k = t >> 5, j = t & 31;
            g_L3[3072 + t] = U3w[j * 32 + k];
        }
    }
}

// ---------------- main-loop GEMM helpers (R8-proven) ----------------
__device__ __forceinline__ void gemmL1(const float* __restrict__ A,
                                       const float* __restrict__ Bm,
                                       const float* __restrict__ Bu,
                                       int i0, int j4, ull (&m)[8][2], ull (&u)[8][2]) {
#pragma unroll
    for (int k = 0; k < 16; k++) {
        float4 a0 = *reinterpret_cast<const float4*>(A + k * P + i0);
        float4 a1 = *reinterpret_cast<const float4*>(A + k * P + i0 + 4);
        ulonglong2 bm = *reinterpret_cast<const ulonglong2*>(Bm + k * 128 + j4);
        ulonglong2 bu = *reinterpret_cast<const ulonglong2*>(Bu + k * 128 + j4);
        ull Ar[8] = {dup2(a0.x), dup2(a0.y), dup2(a0.z), dup2(a0.w),
                     dup2(a1.x), dup2(a1.y), dup2(a1.z), dup2(a1.w)};
#pragma unroll
        for (int r = 0; r < 8; r++) {
            fma2(m[r][0], Ar[r], bm.x);
            fma2(m[r][1], Ar[r], bm.y);
            fma2(u[r][0], Ar[r], bu.x);
            fma2(u[r][1], Ar[r], bu.y);
        }
    }
}
template<int K, int LDB, int UNR>
__device__ __forceinline__ void gemmR8(const float* __restrict__ A,
                                       const float* __restrict__ B,
                                       int i0, int j, ull (&acc)[8]) {
#pragma unroll UNR
    for (int k = 0; k < K; k++) {
        float4 a0 = *reinterpret_cast<const float4*>(A + k * P + i0);
        float4 a1 = *reinterpret_cast<const float4*>(A + k * P + i0 + 4);
        ull b = *reinterpret_cast<const ull*>(B + k * LDB + j);
        ull Ar[8] = {dup2(a0.x), dup2(a0.y), dup2(a0.z), dup2(a0.w),
                     dup2(a1.x), dup2(a1.y), dup2(a1.z), dup2(a1.w)};
#pragma unroll
        for (int r = 0; r < 8; r++) fma2(acc[r], Ar[r], b);
    }
}
template<int K, int LDB, int UNR>
__device__ __forceinline__ void gemmR4(const float* __restrict__ A,
                                       const float* __restrict__ B,
                                       int i0, int j, ull (&acc)[4]) {
#pragma unroll UNR
    for (int k = 0; k < K; k++) {
        float4 a = *reinterpret_cast<const float4*>(A + k * P + i0);
        ull b = *reinterpret_cast<const ull*>(B + k * LDB + j);
        ull Ar[4] = {dup2(a.x), dup2(a.y), dup2(a.z), dup2(a.w)};
#pragma unroll
        for (int r = 0; r < 4; r++) fma2(acc[r], Ar[r], b);
    }
}
__device__ __forceinline__ void pld4(const float* __restrict__ src, int tid, float4 (&r)[4]) {
#pragma unroll
    for (int j = 0; j < 4; j++)
        r[j] = *reinterpret_cast<const float4*>(src + j * 1024 + tid * 4);
}
__device__ __forceinline__ void pst4(float* dst, int tid, const float4 (&r)[4]) {
#pragma unroll
    for (int j = 0; j < 4; j++)
        *reinterpret_cast<float4*>(dst + j * 1024 + tid * 4) = r[j];
}

// ---------------- main kernel (R8 proven loop; xw from g_XW) ----------------
// smem floats (23744 = 94976 B, 2 CTAs/SM):
//   h1s[128*68]@0  h2s[64*68]@8704  h3s[32*68]@13056
//   buf0@15232(4096)  buf1@19328(4096)  sB@23424(320)
__global__ void __launch_bounds__(NTHR, 2)
pcnet_main(const float* __restrict__ U1b, const float* __restrict__ U2b,
           const float* __restrict__ U3b,
           const float* __restrict__ clfw, const float* __restrict__ clfb,
           const int* __restrict__ steps_p,
           float* __restrict__ out) {
    extern __shared__ float sm[];
    float* h1s  = sm;
    float* h2s  = sm + 8704;
    float* h3s  = sm + 13056;
    float* buf0 = sm + 15232;
    float* buf1 = sm + 19328;
    float* sB   = sm + 23424;

    const int tid  = threadIdx.x;
    const int row0 = blockIdx.x * BT;
    const float* const xwg = g_XW + (size_t)blockIdx.x * 8192;   // [128 cols][64 rows]

    const int wid  = tid >> 5, lane = tid & 31;
    const int rg   = ((wid & 1) << 2) + (lane >> 3);   // 0..7
    const int cq   = ((wid >> 1) << 3) + (lane & 7);   // 0..31
    const int i0   = rg * 8;
    const int j4   = cq * 4;      // L1 cols
    const int j2   = cq * 2;      // L2 cols
    const int rg3  = ((wid & 3) << 2) + (lane >> 3);   // 0..15
    const int cq3  = ((wid >> 2) << 3) + (lane & 7);   // 0..15
    const int i03  = rg3 * 4;
    const int j3   = cq3 * 2;

    int steps = *steps_p;
    if (steps < 0 || steps > 64) steps = 5;

    // biases + zero states + first panel
    for (int t = tid; t < 320; t += NTHR) {
        float v;
        if (t < 32) v = g_c3[t];
        else if (t < 64) v = U3b[t - 32];
        else if (t < 128) v = g_c2[t - 64];
        else if (t < 192) v = U2b[t - 128];
        else v = U1b[t - 192];
        sB[t] = v;
    }
    for (int i = tid; i < 15232; i += NTHR) sm[i] = 0.f;
    for (int idx = tid; idx < 1024; idx += NTHR)
        *reinterpret_cast<float4*>(buf0 + idx * 4) = *reinterpret_cast<const float4*>(g_L3 + idx * 4);
    __syncthreads();

    float* cur = buf0;
    float* oth = buf1;

    // ---- step loop: 13 panel slots ----
    for (int s = 0; s < steps; s++) {
        float4 pr[4];

        // slot 0: L3 full panel (W3T | -M3T | U3T)
        ull aA3[4] = {}, aU3[4] = {};
        pld4(g_W22T, tid, pr);
        gemmR4<64, 32, 8>(h2s, cur, i03, j3, aA3);
        gemmR4<32, 32, 8>(h3s, cur + 2048, i03, j3, aA3);
        gemmR4<32, 32, 8>(h3s, cur + 3072, i03, j3, aU3);
        pst4(oth, tid, pr); __syncthreads();
        { float* t = cur; cur = oth; oth = t; }

        // ---- update h3 ----
        {
            float cc0 = sB[j3], cc1 = sB[j3 + 1];
            float ub0 = sB[32 + j3], ub1 = sB[32 + j3 + 1];
            float4 h0 = *reinterpret_cast<float4*>(h3s + j3 * P + i03);
            float4 h1v = *reinterpret_cast<float4*>(h3s + (j3 + 1) * P + i03);
#pragma unroll
            for (int r = 0; r < 4; r++) {
                float a0, a1, u0, u1;
                up2(aA3[r], a0, a1); up2(aU3[r], u0, u1);
                addf4(h0, r, ftanh(a0 + cc0) + ftanh(u0 + ub0));
                addf4(h1v, r, ftanh(a1 + cc1) + ftanh(u1 + ub1));
            }
            *reinterpret_cast<float4*>(h3s + j3 * P + i03) = h0;
            *reinterpret_cast<float4*>(h3s + (j3 + 1) * P + i03) = h1v;
        }

        // slots 1-3: concat [h1;h2] @ [W2T;-M2T], K=64 per slot
        ull aA2[8] = {};
#pragma unroll
        for (int p = 0; p < 3; p++) {
            const float* Ap = (p == 0) ? h1s : (p == 1) ? (h1s + 64 * P) : h2s;
            const float* nx = (p < 2) ? (g_W22T + (p + 1) * 4096) : g_U2T;
            pld4(nx, tid, pr);
            gemmR8<64, 64, 8>(Ap, cur, i0, j2, aA2);
            pst4(oth, tid, pr); __syncthreads();
            float* t = cur; cur = oth; oth = t;
        }
        // slot 4: U2T (K=64)
        ull aU2[8] = {};
        pld4(g_L1P, tid, pr);
        gemmR8<64, 64, 8>(h2s, cur, i0, j2, aU2);
        pst4(oth, tid, pr); __syncthreads();
        { float* t = cur; cur = oth; oth = t; }

        // ---- update h2 ----
        {
            float cc0 = sB[64 + j2], cc1 = sB[64 + j2 + 1];
            float ub0 = sB[128 + j2], ub1 = sB[128 + j2 + 1];
            float4 ha0 = *reinterpret_cast<float4*>(h2s + j2 * P + i0);
            float4 ha1 = *reinterpret_cast<float4*>(h2s + j2 * P + i0 + 4);
            float4 hb0 = *reinterpret_cast<float4*>(h2s + (j2 + 1) * P + i0);
            float4 hb1 = *reinterpret_cast<float4*>(h2s + (j2 + 1) * P + i0 + 4);
#pragma unroll
            for (int r = 0; r < 8; r++) {
                float a0, a1, u0, u1;
                up2(aA2[r], a0, a1); up2(aU2[r], u0, u1);
                float d0 = ftanh(a0 + cc0) + ftanh(u0 + ub0);
                float d1 = ftanh(a1 + cc1) + ftanh(u1 + ub1);
                if (r < 4) { addf4(ha0, r, d0); addf4(hb0, r, d1); }
                else       { addf4(ha1, r - 4, d0); addf4(hb1, r - 4, d1); }
            }
            *reinterpret_cast<float4*>(h2s + j2 * P + i0)           = ha0;
            *reinterpret_cast<float4*>(h2s + j2 * P + i0 + 4)       = ha1;
            *reinterpret_cast<float4*>(h2s + (j2 + 1) * P + i0)     = hb0;
            *reinterpret_cast<float4*>(h2s + (j2 + 1) * P + i0 + 4) = hb1;
        }

        // slots 5-12: L1 paired panels (-M1T | U1T), K=16 each
        ull aM1[8][2] = {}, aU1[8][2] = {};
#pragma unroll 1
        for (int p = 0; p < 8; p++) {
            const float* nx = (p < 7) ? (g_L1P + (p + 1) * 4096) : g_L3;
            pld4(nx, tid, pr);
            gemmL1(h1s + 16 * p * P, cur, cur + 2048, i0, j4, aM1, aU1);
            pst4(oth, tid, pr); __syncthreads();
            float* t = cur; cur = oth; oth = t;
        }

        // ---- update h1 (xw streamed from L2-resident g_XW) ----
#pragma unroll
        for (int cp = 0; cp < 2; cp++) {
            int col = j4 + 2 * cp;
            float ub0 = sB[192 + col], ub1 = sB[192 + col + 1];
            float4 xa0 = *reinterpret_cast<const float4*>(xwg + col * 64 + i0);
            float4 xa1 = *reinterpret_cast<const float4*>(xwg + col * 64 + i0 + 4);
            float4 xb0 = *reinterpret_cast<const float4*>(xwg + (col + 1) * 64 + i0);
            float4 xb1 = *reinterpret_cast<const float4*>(xwg + (col + 1) * 64 + i0 + 4);
            float4 ha0 = *reinterpret_cast<float4*>(h1s + col * P + i0);
            float4 ha1 = *reinterpret_cast<float4*>(h1s + col * P + i0 + 4);
            float4 hb0 = *reinterpret_cast<float4*>(h1s + (col + 1) * P + i0);
            float4 hb1 = *reinterpret_cast<float4*>(h1s + (col + 1) * P + i0 + 4);
#pragma unroll
            for (int r = 0; r < 8; r++) {
                float m0, m1, u0, u1;
                up2(aM1[r][cp], m0, m1); up2(aU1[r][cp], u0, u1);
                float xw0 = (r < 4) ? getf4(xa0, r) : getf4(xa1, r - 4);
                float xw1 = (r < 4) ? getf4(xb0, r) : getf4(xb1, r - 4);
                float d0 = ftanh(xw0 + m0) + ftanh(u0 + ub0);
                float d1 = ftanh(xw1 + m1) + ftanh(u1 + ub1);
                if (r < 4) { addf4(ha0, r, d0); addf4(hb0, r, d1); }
                else       { addf4(ha1, r - 4, d0); addf4(hb1, r - 4, d1); }
            }
            *reinterpret_cast<float4*>(h1s + col * P + i0)           = ha0;
            *reinterpret_cast<float4*>(h1s + col * P + i0 + 4)       = ha1;
            *reinterpret_cast<float4*>(h1s + (col + 1) * P + i0)     = hb0;
            *reinterpret_cast<float4*>(h1s + (col + 1) * P + i0 + 4) = hb1;
        }
        // h1 writes ordered before next step's first h1s read (slot 1) by the
        // next step's slot-0 barrier; h2/h3 writes covered likewise.
    }
    __syncthreads();

    // ---- classifier: out = h3 @ clf^T + clf_b ----
    for (int idx = tid; idx < BT * 10; idx += NTHR) {
        int r = idx / 10, cc = idx - r * 10;
        float sacc = clfb[cc];
#pragma unroll
        for (int k = 0; k < 32; k++) sacc += h3s[k * P + r] * clfw[cc * 32 + k];
        out[(size_t)(row0 + r) * 10 + cc] = sacc;
    }
}

// ---------------- launch ----------------
extern "C" void kernel_launch(void* const* d_in, const int* in_sizes, int n_in,
                              void* d_out, int out_size) {
    const float* x    = (const float*)d_in[0];
    const float* W1w  = (const float*)d_in[1];
    const float* W1b  = (const float*)d_in[2];
    const float* U1w  = (const float*)d_in[3];
    const float* U1b  = (const float*)d_in[4];
    const float* W2w  = (const float*)d_in[5];
    const float* W2b  = (const float*)d_in[6];
    const float* U2w  = (const float*)d_in[7];
    const float* U2b  = (const float*)d_in[8];
    const float* W3w  = (const float*)d_in[9];
    const float* W3b  = (const float*)d_in[10];
    const float* U3w  = (const float*)d_in[11];
    const float* U3b  = (const float*)d_in[12];
    const float* fb3w = (const float*)d_in[13];
    const float* fb3b = (const float*)d_in[14];
    const float* fb2w = (const float*)d_in[15];
    const float* fb2b = (const float*)d_in[16];
    const float* fb1w = (const float*)d_in[17];
    const float* fb1b = (const float*)d_in[18];
    const float* clfw = (const float*)d_in[19];
    const float* clfb = (const float*)d_in[20];
    const int*   stp  = (const int*)d_in[21];

    int B = in_sizes[0] / 784;
    if (B > 65536) B = 65536;   // g_XW capacity guard

    prep_all<<<256, 128>>>(W1w, W1b, U1w, W2w, W2b, U2w, W3w, W3b, U3w,
                           fb3w, fb3b, fb2w, fb2b, fb1w, fb1b);

    const int p1_smem = 4 * 128 * PW * 2 + 512;   // 139776 B
    cudaFuncSetAttribute(phase1_mma, cudaFuncAttributeMaxDynamicSharedMemorySize, p1_smem);
    phase1_mma<<<B / 128, 256, p1_smem>>>(x);

    const int smem_bytes = 23744 * 4;   // 94976 -> 2 CTAs/SM
    cudaFuncSetAttribute(pcnet_main, cudaFuncAttributeMaxDynamicSharedMemorySize, smem_bytes);
    pcnet_main<<<B / BT, NTHR, smem_bytes>>>(U1b, U2b, U3b, clfw, clfb, stp, (float*)d_out);
}

// round 17
// speedup vs baseline: 1.6582x; 1.1549x over previous
#include <cuda_runtime.h>
#include <cuda_bf16.h>
#include <cstdint>

#define BT   64
#define NTHR 256
#define PS   240     // state pitch (f32): h1 0..127 | h2 128..191 | h3 192..223
#define PA   248     // A-buffer pitch (bf16)
#define PP   24      // panel pitch (bf16)
typedef unsigned long long ull;

// ---------------- persistent device scratch ----------------
// Interleaved-stacked bf16 weights (hi/lo split). Row mapping per group:
//  G1 (K=128): rows 16*(j>>3)+(j&7) = -M1[j], +8 = U1[j] (j<128); rows 256+j = W2[j] (j<64)
//  G2 (K=64):  rows 16*(j>>3)+(j&7) = -M2[j], +8 = U2[j] (j<64);  rows 128+j = W3[j] (j<32)
//  G3 (K=32):  rows 16*(j>>3)+(j&7) = -M3[j], +8 = U3[j] (j<32)
__device__ __align__(16) __nv_bfloat16 g_G1h[320*128];
__device__ __align__(16) __nv_bfloat16 g_G1l[320*128];
__device__ __align__(16) __nv_bfloat16 g_G2h[160*64];
__device__ __align__(16) __nv_bfloat16 g_G2l[160*64];
__device__ __align__(16) __nv_bfloat16 g_G3h[64*32];
__device__ __align__(16) __nv_bfloat16 g_G3l[64*32];
__device__ __align__(16) float g_c1[128];
__device__ __align__(16) float g_c2[64];
__device__ __align__(16) float g_c3[32];
__device__ __align__(16) float g_XW[65536*128];  // xw, ROW-major per 64-row tile: [r][col]
__device__ __align__(16) __nv_bfloat16 g_W1hT[128*896];  // phase1 W1^T bf16 split
__device__ __align__(16) __nv_bfloat16 g_W1lT[128*896];

// ---------------- helpers ----------------
__device__ __forceinline__ float ftanh(float x) {
    float e, r;
    asm("ex2.approx.ftz.f32 %0, %1;" : "=f"(e) : "f"(x * 2.8853900817779268f));
    asm("rcp.approx.ftz.f32 %0, %1;" : "=f"(r) : "f"(e + 1.0f));
    return fmaf(-2.0f, r, 1.0f);
}
__device__ __forceinline__ void hmma(float (&c)[4],
                                     uint32_t a0, uint32_t a1, uint32_t a2, uint32_t a3,
                                     uint32_t b0, uint32_t b1) {
    asm volatile(
        "mma.sync.aligned.m16n8k16.row.col.f32.bf16.bf16.f32 "
        "{%0,%1,%2,%3}, {%4,%5,%6,%7}, {%8,%9}, {%0,%1,%2,%3};"
        : "+f"(c[0]), "+f"(c[1]), "+f"(c[2]), "+f"(c[3])
        : "r"(a0), "r"(a1), "r"(a2), "r"(a3), "r"(b0), "r"(b1));
}
__device__ __forceinline__ uint32_t pack_bf16x2(float a, float b) {
    __nv_bfloat162 v = __floats2bfloat162_rn(a, b);
    return *reinterpret_cast<uint32_t*>(&v);
}
__device__ __forceinline__ void wsplit(__nv_bfloat16* H, __nv_bfloat16* L, int idx, float v) {
    __nv_bfloat16 h = __float2bfloat16(v);
    H[idx] = h;
    L[idx] = __float2bfloat16(v - __bfloat162float(h));
}

// panel staging relay: load chunk c of [N][K] hi/lo weights into regs / store to panel
__device__ __forceinline__ void pldP(const __nv_bfloat16* Gh, const __nv_bfloat16* Gl,
                                     int K, int N, int c, int tid, uint2 (&pr)[10], int cnt) {
    const int half = N * 4;   // uint2 per split
#pragma unroll
    for (int q = 0; q < 10; q++) {
        if (q >= cnt) break;
        int idx = q * 256 + tid;
        const __nv_bfloat16* src = (idx < half) ? Gh : Gl;
        int m = (idx < half) ? idx : idx - half;
        int n = m >> 2, quad = m & 3;
        pr[q] = *reinterpret_cast<const uint2*>(src + n * K + c * 16 + quad * 4);
    }
}
__device__ __forceinline__ void pstP(__nv_bfloat16* panel, int N, int tid,
                                     const uint2 (&pr)[10], int cnt) {
    const int half = N * 4;
#pragma unroll
    for (int q = 0; q < 10; q++) {
        if (q >= cnt) break;
        int idx = q * 256 + tid;
        int split = (idx < half) ? 0 : 1;
        int m = idx - split * half;
        int n = m >> 2, quad = m & 3;
        *reinterpret_cast<uint2*>(panel + split * N * PP + n * PP + quad * 4) = pr[q];
    }
}

// one k16 GEMM slot over TN n8-tiles (hi*hi + hi*lo + lo*hi)
template<int TN>
__device__ __forceinline__ void gemmHM(const __nv_bfloat16* Ah, const __nv_bfloat16* Al,
                                       const __nv_bfloat16* panel, int N, int kb,
                                       int arow, int nh, int gid, int tq,
                                       float (&acc)[TN][4]) {
    const __nv_bfloat16* ar = Ah + arow * PA + kb + tq * 2;
    const __nv_bfloat16* al = Al + arow * PA + kb + tq * 2;
    uint32_t ah0 = *reinterpret_cast<const uint32_t*>(ar);
    uint32_t ah1 = *reinterpret_cast<const uint32_t*>(ar + 8 * PA);
    uint32_t ah2 = *reinterpret_cast<const uint32_t*>(ar + 8);
    uint32_t ah3 = *reinterpret_cast<const uint32_t*>(ar + 8 * PA + 8);
    uint32_t al0 = *reinterpret_cast<const uint32_t*>(al);
    uint32_t al1 = *reinterpret_cast<const uint32_t*>(al + 8 * PA);
    uint32_t al2 = *reinterpret_cast<const uint32_t*>(al + 8);
    uint32_t al3 = *reinterpret_cast<const uint32_t*>(al + 8 * PA + 8);
    const __nv_bfloat16* ph = panel;
    const __nv_bfloat16* pl = panel + N * PP;
#pragma unroll
    for (int l = 0; l < TN; l++) {
        int colb = (nh * TN + l) * 8 + gid;
        const __nv_bfloat16* bh = ph + colb * PP + tq * 2;
        const __nv_bfloat16* bl = pl + colb * PP + tq * 2;
        uint32_t bh0 = *reinterpret_cast<const uint32_t*>(bh);
        uint32_t bh1 = *reinterpret_cast<const uint32_t*>(bh + 8);
        uint32_t bl0 = *reinterpret_cast<const uint32_t*>(bl);
        uint32_t bl1 = *reinterpret_cast<const uint32_t*>(bl + 8);
        hmma(acc[l], ah0, ah1, ah2, ah3, bh0, bh1);
        hmma(acc[l], ah0, ah1, ah2, ah3, bl0, bl1);
        hmma(acc[l], al0, al1, al2, al3, bh0, bh1);
    }
}

// ---------------- phase-1 tensor kernel (validated; epilogue now row-major) ----------------
#define PW 136
__global__ void __launch_bounds__(256, 1)
phase1_mma(const float* __restrict__ x) {
    extern __shared__ __nv_bfloat16 sb16[];
    __nv_bfloat16* xh = sb16;
    __nv_bfloat16* xl = xh + 128 * PW;
    __nv_bfloat16* wh = xl + 128 * PW;
    __nv_bfloat16* wl = wh + 128 * PW;
    float* c1s = reinterpret_cast<float*>(wl + 128 * PW);

    const int tid = threadIdx.x;
    const int wid = tid >> 5, lane = tid & 31;
    const int gid = lane >> 2;
    const int tq  = lane & 3;
    const int row0 = blockIdx.x * 128;

    for (int t = tid; t < 128; t += 256) c1s[t] = g_c1[t];

    float acc[16][4];
#pragma unroll
    for (int n = 0; n < 16; n++)
#pragma unroll
        for (int q = 0; q < 4; q++) acc[n][q] = 0.f;

    for (int c = 0; c < 7; c++) {
        __syncthreads();
        for (int idx = tid; idx < 4096; idx += 256) {
            int n = idx >> 5, kq = (idx & 31) * 4;
            *reinterpret_cast<uint2*>(wh + n * PW + kq) =
                *reinterpret_cast<const uint2*>(g_W1hT + n * 896 + c * 128 + kq);
            *reinterpret_cast<uint2*>(wl + n * PW + kq) =
                *reinterpret_cast<const uint2*>(g_W1lT + n * 896 + c * 128 + kq);
        }
        for (int idx = tid; idx < 4096; idx += 256) {
            int row = idx >> 5, kq = (idx & 31) * 4;
            float4 v = make_float4(0.f, 0.f, 0.f, 0.f);
            if (c < 6 || kq < 16)
                v = *reinterpret_cast<const float4*>(
                        x + (size_t)(row0 + row) * 784 + c * 128 + kq);
            float h0 = __bfloat162float(__float2bfloat16(v.x));
            float h1 = __bfloat162float(__float2bfloat16(v.y));
            float h2 = __bfloat162float(__float2bfloat16(v.z));
            float h3 = __bfloat162float(__float2bfloat16(v.w));
            uint2 ph = make_uint2(pack_bf16x2(h0, h1), pack_bf16x2(h2, h3));
            uint2 pl = make_uint2(pack_bf16x2(v.x - h0, v.y - h1),
                                  pack_bf16x2(v.z - h2, v.w - h3));
            *reinterpret_cast<uint2*>(xh + row * PW + kq) = ph;
            *reinterpret_cast<uint2*>(xl + row * PW + kq) = pl;
        }
        __syncthreads();

        const int arow = 16 * wid + gid;
#pragma unroll 2
        for (int s = 0; s < 8; s++) {
            const int k0 = s * 16;
            const __nv_bfloat16* ar = xh + arow * PW + k0 + tq * 2;
            const __nv_bfloat16* al = xl + arow * PW + k0 + tq * 2;
            uint32_t ah0 = *reinterpret_cast<const uint32_t*>(ar);
            uint32_t ah1 = *reinterpret_cast<const uint32_t*>(ar + 8 * PW);
            uint32_t ah2 = *reinterpret_cast<const uint32_t*>(ar + 8);
            uint32_t ah3 = *reinterpret_cast<const uint32_t*>(ar + 8 * PW + 8);
            uint32_t al0 = *reinterpret_cast<const uint32_t*>(al);
            uint32_t al1 = *reinterpret_cast<const uint32_t*>(al + 8 * PW);
            uint32_t al2 = *reinterpret_cast<const uint32_t*>(al + 8);
            uint32_t al3 = *reinterpret_cast<const uint32_t*>(al + 8 * PW + 8);
#pragma unroll
            for (int nt = 0; nt < 16; nt++) {
                const int colb = nt * 8 + gid;
                const __nv_bfloat16* bh = wh + colb * PW + k0 + tq * 2;
                const __nv_bfloat16* bl = wl + colb * PW + k0 + tq * 2;
                uint32_t bh0 = *reinterpret_cast<const uint32_t*>(bh);
                uint32_t bh1 = *reinterpret_cast<const uint32_t*>(bh + 8);
                uint32_t bl0 = *reinterpret_cast<const uint32_t*>(bl);
                uint32_t bl1 = *reinterpret_cast<const uint32_t*>(bl + 8);
                hmma(acc[nt], ah0, ah1, ah2, ah3, bh0, bh1);
                hmma(acc[nt], ah0, ah1, ah2, ah3, bl0, bl1);
                hmma(acc[nt], al0, al1, al2, al3, bh0, bh1);
            }
        }
    }

    // epilogue: ROW-major per 64-row tile: g_XW[tile*8192 + r*128 + col]
    const int r0 = 16 * wid + gid;
    const int r1 = r0 + 8;
    const size_t ob0 = (size_t)(blockIdx.x * 2 + (r0 >> 6)) * 8192 + (size_t)(r0 & 63) * 128;
    const size_t ob1 = (size_t)(blockIdx.x * 2 + (r1 >> 6)) * 8192 + (size_t)(r1 & 63) * 128;
#pragma unroll
    for (int nt = 0; nt < 16; nt++) {
        int c0 = nt * 8 + tq * 2;
        g_XW[ob0 + c0]     = acc[nt][0] + c1s[c0];
        g_XW[ob0 + c0 + 1] = acc[nt][1] + c1s[c0 + 1];
        g_XW[ob1 + c0]     = acc[nt][2] + c1s[c0];
        g_XW[ob1 + c0 + 1] = acc[nt][3] + c1s[c0 + 1];
    }
}

// ---------------- prep kernel ----------------
__global__ void prep_all(const float* __restrict__ W1w, const float* __restrict__ W1b,
                         const float* __restrict__ U1w,
                         const float* __restrict__ W2w, const float* __restrict__ W2b,
                         const float* __restrict__ U2w,
                         const float* __restrict__ W3w, const float* __restrict__ W3b,
                         const float* __restrict__ U3w,
                         const float* __restrict__ fb3w, const float* __restrict__ fb3b,
                         const float* __restrict__ fb2w, const float* __restrict__ fb2b,
                         const float* __restrict__ fb1w, const float* __restrict__ fb1b) {
    __shared__ float row_s[784];
    __shared__ float red_s[128];
    const int bid = blockIdx.x;
    const int tid = threadIdx.x;   // 128

    if (bid < 128) {
        const int j = bid;
        for (int d = tid; d < 784; d += 128) row_s[d] = W1w[j * 784 + d];
        __syncthreads();
        {
            const int k = tid;
            float s0 = 0.f, s1 = 0.f, s2 = 0.f, s3 = 0.f;
            float s4 = 0.f, s5 = 0.f, s6 = 0.f, s7 = 0.f;
            for (int d = 0; d < 784; d += 8) {
                s0 += row_s[d + 0] * fb1w[(d + 0) * 128 + k];
                s1 += row_s[d + 1] * fb1w[(d + 1) * 128 + k];
                s2 += row_s[d + 2] * fb1w[(d + 2) * 128 + k];
                s3 += row_s[d + 3] * fb1w[(d + 3) * 128 + k];
                s4 += row_s[d + 4] * fb1w[(d + 4) * 128 + k];
                s5 += row_s[d + 5] * fb1w[(d + 5) * 128 + k];
                s6 += row_s[d + 6] * fb1w[(d + 6) * 128 + k];
                s7 += row_s[d + 7] * fb1w[(d + 7) * 128 + k];
            }
            float s = ((s0 + s1) + (s2 + s3)) + ((s4 + s5) + (s6 + s7));
            int row = 16 * (j >> 3) + (j & 7);
            wsplit(g_G1h, g_G1l, row * 128 + k, -s);
        }
        float p0 = 0.f, p1 = 0.f, p2 = 0.f, p3 = 0.f;
        for (int d = tid; d < 784; d += 512) {
            p0 += row_s[d] * fb1b[d];
            if (d + 128 < 784) p1 += row_s[d + 128] * fb1b[d + 128];
            if (d + 256 < 784) p2 += row_s[d + 256] * fb1b[d + 256];
            if (d + 384 < 784) p3 += row_s[d + 384] * fb1b[d + 384];
        }
        red_s[tid] = (p0 + p1) + (p2 + p3);
        __syncthreads();
        for (int off = 64; off > 0; off >>= 1) {
            if (tid < off) red_s[tid] += red_s[tid + off];
            __syncthreads();
        }
        if (tid == 0) g_c1[j] = W1b[j] - red_s[0];
    } else if (bid < 192) {
        const int j = bid - 128;
        for (int d = tid; d < 128; d += 128) row_s[d] = W2w[j * 128 + d];
        __syncthreads();
        if (tid < 64) {
            const int k = tid;
            float s0 = 0.f, s1 = 0.f, s2 = 0.f, s3 = 0.f;
            for (int d = 0; d < 128; d += 4) {
                s0 += row_s[d + 0] * fb2w[(d + 0) * 64 + k];
                s1 += row_s[d + 1] * fb2w[(d + 1) * 64 + k];
                s2 += row_s[d + 2] * fb2w[(d + 2) * 64 + k];
                s3 += row_s[d + 3] * fb2w[(d + 3) * 64 + k];
            }
            int row = 16 * (j >> 3) + (j & 7);
            wsplit(g_G2h, g_G2l, row * 64 + k, -((s0 + s1) + (s2 + s3)));
        }
        float ps = 0.f;
        for (int d = tid; d < 128; d += 128) ps += row_s[d] * fb2b[d];
        red_s[tid] = ps;
        __syncthreads();
        for (int off = 64; off > 0; off >>= 1) {
            if (tid < off) red_s[tid] += red_s[tid + off];
            __syncthreads();
        }
        if (tid == 0) g_c2[j] = W2b[j] - red_s[0];
    } else if (bid < 224) {
        const int j = bid - 192;
        for (int d = tid; d < 64; d += 128) row_s[d] = W3w[j * 64 + d];
        __syncthreads();
        if (tid < 32) {
            const int k = tid;
            float s0 = 0.f, s1 = 0.f, s2 = 0.f, s3 = 0.f;
            for (int d = 0; d < 64; d += 4) {
                s0 += row_s[d + 0] * fb3w[(d + 0) * 32 + k];
                s1 += row_s[d + 1] * fb3w[(d + 1) * 32 + k];
                s2 += row_s[d + 2] * fb3w[(d + 2) * 32 + k];
                s3 += row_s[d + 3] * fb3w[(d + 3) * 32 + k];
            }
            int row = 16 * (j >> 3) + (j & 7);
            wsplit(g_G3h, g_G3l, row * 32 + k, -((s0 + s1) + (s2 + s3)));
        }
        float ps = 0.f;
        for (int d = tid; d < 64; d += 128) ps += row_s[d] * fb3b[d];
        red_s[tid] = ps;
        __syncthreads();
        for (int off = 64; off > 0; off >>= 1) {
            if (tid < off) red_s[tid] += red_s[tid + off];
            __syncthreads();
        }
        if (tid == 0) g_c3[j] = W3b[j] - red_s[0];
    } else {
        const int idx0 = (bid - 224) * 128 + tid;
        const int stride = 32 * 128;
        for (int t = idx0; t < 128 * 896; t += stride) {          // W1^T split (phase1)
            int n = t / 896, k = t - n * 896;
            float v = (k < 784) ? W1w[n * 784 + k] : 0.f;
            __nv_bfloat16 h = __float2bfloat16(v);
            g_W1hT[t] = h;
            g_W1lT[t] = __float2bfloat16(v - __bfloat162float(h));
        }
        for (int t = idx0; t < 128 * 128; t += stride) {          // U1 -> G1
            int j = t >> 7, k = t & 127;
            int row = 16 * (j >> 3) + 8 + (j & 7);
            wsplit(g_G1h, g_G1l, row * 128 + k, U1w[j * 128 + k]);
        }
        for (int t = idx0; t < 64 * 128; t += stride) {           // W2 -> G1
            int j = t >> 7, k = t & 127;
            wsplit(g_G1h, g_G1l, (256 + j) * 128 + k, W2w[j * 128 + k]);
        }
        for (int t = idx0; t < 64 * 64; t += stride) {            // U2 -> G2
            int j = t >> 6, k = t & 63;
            int row = 16 * (j >> 3) + 8 + (j & 7);
            wsplit(g_G2h, g_G2l, row * 64 + k, U2w[j * 64 + k]);
        }
        for (int t = idx0; t < 32 * 64; t += stride) {            // W3 -> G2
            int j = t >> 6, k = t & 63;
            wsplit(g_G2h, g_G2l, (128 + j) * 64 + k, W3w[j * 64 + k]);
        }
        for (int t = idx0; t < 32 * 32; t += stride) {            // U3 -> G3
            int j = t >> 5, k = t & 31;
            int row = 16 * (j >> 3) + 8 + (j & 7);
            wsplit(g_G3h, g_G3l, row * 32 + k, U3w[j * 32 + k]);
        }
    }
}

// ---------------- main kernel: full HMMA loop ----------------
// smem floats (53568 = 214272 B, 1 CTA/SM):
//   S[64][240]@0 (15360)  Cw2[64][68]@15360 (4352)  Cw3[64][36]@19712 (2304)
//   sB@22016 (320)  buf0@22336 (7680)  buf1@30016 (7680)
//   Ah@37696 (7936 fl = [64][248] bf16)  Al@45632 (7936)
__global__ void __launch_bounds__(NTHR, 1)
pcnet_main(const float* __restrict__ U1b, const float* __restrict__ U2b,
           const float* __restrict__ U3b,
           const float* __restrict__ clfw, const float* __restrict__ clfb,
           const int* __restrict__ steps_p,
           float* __restrict__ out) {
    extern __shared__ float sm[];
    float* S    = sm;
    float* Cw2  = sm + 15360;
    float* Cw3  = sm + 19712;
    float* sB   = sm + 22016;
    __nv_bfloat16* buf0 = reinterpret_cast<__nv_bfloat16*>(sm + 22336);
    __nv_bfloat16* buf1 = reinterpret_cast<__nv_bfloat16*>(sm + 30016);
    __nv_bfloat16* Ah   = reinterpret_cast<__nv_bfloat16*>(sm + 37696);
    __nv_bfloat16* Al   = reinterpret_cast<__nv_bfloat16*>(sm + 45632);

    const int tid  = threadIdx.x;
    const int row0 = blockIdx.x * BT;
    const float* const xwg = g_XW + (size_t)blockIdx.x * 8192;   // [64 r][128 col]

    const int wid = tid >> 5, lane = tid & 31;
    const int mt  = wid & 3;        // m16 tile
    const int nh  = wid >> 2;       // n half
    const int gid = lane >> 2;
    const int tq  = lane & 3;
    const int arow = mt * 16 + gid;
    const int r0 = arow, r1 = arow + 8;

    int steps = *steps_p;
    if (steps < 0 || steps > 64) steps = 5;

    // biases: [0..127]=U1b [128..191]=c2 [192..255]=U2b [256..287]=c3 [288..319]=U3b
    for (int t = tid; t < 320; t += NTHR) {
        float v;
        if (t < 128) v = U1b[t];
        else if (t < 192) v = g_c2[t - 128];
        else if (t < 256) v = U2b[t - 192];
        else if (t < 288) v = g_c3[t - 256];
        else v = U3b[t - 288];
        sB[t] = v;
    }
    // zero states
    for (int i = tid; i < 15360; i += NTHR) S[i] = 0.f;
    // prologue: stage G1 chunk 0 into buf0
    {
        uint2 pr[10];
        pldP(g_G1h, g_G1l, 128, 320, 0, tid, pr, 10);
        pstP(buf0, 320, tid, pr, 10);
    }
    __syncthreads();

    __nv_bfloat16* cur = buf0;
    __nv_bfloat16* oth = buf1;

    for (int s = 0; s < steps; s++) {
        // ---- convert states -> bf16 hi/lo A buffers ----
        for (int idx = tid; idx < 64 * 56; idx += NTHR) {
            int r = idx / 56, c4 = (idx - r * 56) * 4;
            float4 v = *reinterpret_cast<const float4*>(S + r * PS + c4);
            float h0 = __bfloat162float(__float2bfloat16(v.x));
            float h1 = __bfloat162float(__float2bfloat16(v.y));
            float h2 = __bfloat162float(__float2bfloat16(v.z));
            float h3 = __bfloat162float(__float2bfloat16(v.w));
            *reinterpret_cast<uint2*>(Ah + r * PA + c4) =
                make_uint2(pack_bf16x2(h0, h1), pack_bf16x2(h2, h3));
            *reinterpret_cast<uint2*>(Al + r * PA + c4) =
                make_uint2(pack_bf16x2(v.x - h0, v.y - h1), pack_bf16x2(v.z - h2, v.w - h3));
        }
        __syncthreads();

        // ---- G1: A=h1 (K=128), 8 slots ----
        float aG1[20][4] = {};
#pragma unroll 1
        for (int c = 0; c < 8; c++) {
            uint2 pr[10];
            if (c < 7) pldP(g_G1h, g_G1l, 128, 320, c + 1, tid, pr, 10);
            else       pldP(g_G2h, g_G2l, 64, 160, 0, tid, pr, 5);
            gemmHM<20>(Ah, Al, cur, 320, c * 16, arow, nh, gid, tq, aG1);
            if (c < 7) pstP(oth, 320, tid, pr, 10);
            else       pstP(oth, 160, tid, pr, 5);
            __syncthreads();
            __nv_bfloat16* t = cur; cur = oth; oth = t;
        }

        // ---- epilogue 1: update h1, stash W2 partials ----
        if (nh == 0) {
#pragma unroll
            for (int p = 0; p < 10; p++) {
                int j = p * 8 + tq * 2;
                float* aM = aG1[2 * p];
                float* aU = aG1[2 * p + 1];
                float2 x0 = *reinterpret_cast<const float2*>(xwg + r0 * 128 + j);
                float2 x1 = *reinterpret_cast<const float2*>(xwg + r1 * 128 + j);
                float2 h0 = *reinterpret_cast<float2*>(S + r0 * PS + j);
                float2 h1 = *reinterpret_cast<float2*>(S + r1 * PS + j);
                float ub0 = sB[j], ub1 = sB[j + 1];
                h0.x += ftanh(x0.x + aM[0]) + ftanh(aU[0] + ub0);
                h0.y += ftanh(x0.y + aM[1]) + ftanh(aU[1] + ub1);
                h1.x += ftanh(x1.x + aM[2]) + ftanh(aU[2] + ub0);
                h1.y += ftanh(x1.y + aM[3]) + ftanh(aU[3] + ub1);
                *reinterpret_cast<float2*>(S + r0 * PS + j) = h0;
                *reinterpret_cast<float2*>(S + r1 * PS + j) = h1;
            }
        } else {
#pragma unroll
            for (int p = 10; p < 16; p++) {
                int l = 2 * (p - 10);
                int j = p * 8 + tq * 2;
                float* aM = aG1[l];
                float* aU = aG1[l + 1];
                float2 x0 = *reinterpret_cast<const float2*>(xwg + r0 * 128 + j);
                float2 x1 = *reinterpret_cast<const float2*>(xwg + r1 * 128 + j);
                float2 h0 = *reinterpret_cast<float2*>(S + r0 * PS + j);
                float2 h1 = *reinterpret_cast<float2*>(S + r1 * PS + j);
                float ub0 = sB[j], ub1 = sB[j + 1];
                h0.x += ftanh(x0.x + aM[0]) + ftanh(aU[0] + ub0);
                h0.y += ftanh(x0.y + aM[1]) + ftanh(aU[1] + ub1);
                h1.x += ftanh(x1.x + aM[2]) + ftanh(aU[2] + ub0);
                h1.y += ftanh(x1.y + aM[3]) + ftanh(aU[3] + ub1);
                *reinterpret_cast<float2*>(S + r0 * PS + j) = h0;
                *reinterpret_cast<float2*>(S + r1 * PS + j) = h1;
            }
#pragma unroll
            for (int w = 0; w < 8; w++) {
                int l = 12 + w;
                int j = w * 8 + tq * 2;
                *reinterpret_cast<float2*>(Cw2 + r0 * 68 + j) = make_float2(aG1[l][0], aG1[l][1]);
                *reinterpret_cast<float2*>(Cw2 + r1 * 68 + j) = make_float2(aG1[l][2], aG1[l][3]);
            }
        }

        // ---- G2: A=h2 (K=64, k-off 128), 4 slots ----
        float aG2[10][4] = {};
#pragma unroll 1
        for (int c = 0; c < 4; c++) {
            uint2 pr[10];
            if (c < 3) pldP(g_G2h, g_G2l, 64, 160, c + 1, tid, pr, 5);
            else       pldP(g_G3h, g_G3l, 32, 64, 0, tid, pr, 2);
            gemmHM<10>(Ah, Al, cur, 160, 128 + c * 16, arow, nh, gid, tq, aG2);
            if (c < 3) pstP(oth, 160, tid, pr, 5);
            else       pstP(oth, 64, tid, pr, 2);
            __syncthreads();
            __nv_bfloat16* t = cur; cur = oth; oth = t;
        }

        // ---- epilogue 2: update h2, stash W3 partials ----
        if (nh == 0) {
#pragma unroll
            for (int p = 0; p < 5; p++) {
                int j = p * 8 + tq * 2;
                float* aM = aG2[2 * p];
                float* aU = aG2[2 * p + 1];
                float2 w0 = *reinterpret_cast<const float2*>(Cw2 + r0 * 68 + j);
                float2 w1 = *reinterpret_cast<const float2*>(Cw2 + r1 * 68 + j);
                float2 h0 = *reinterpret_cast<float2*>(S + r0 * PS + 128 + j);
                float2 h1 = *reinterpret_cast<float2*>(S + r1 * PS + 128 + j);
                float cc0 = sB[128 + j], cc1 = sB[128 + j + 1];
                float ub0 = sB[192 + j], ub1 = sB[192 + j + 1];
                h0.x += ftanh(w0.x + aM[0] + cc0) + ftanh(aU[0] + ub0);
                h0.y += ftanh(w0.y + aM[1] + cc1) + ftanh(aU[1] + ub1);
                h1.x += ftanh(w1.x + aM[2] + cc0) + ftanh(aU[2] + ub0);
                h1.y += ftanh(w1.y + aM[3] + cc1) + ftanh(aU[3] + ub1);
                *reinterpret_cast<float2*>(S + r0 * PS + 128 + j) = h0;
                *reinterpret_cast<float2*>(S + r1 * PS + 128 + j) = h1;
            }
        } else {
#pragma unroll
            for (int p = 5; p < 8; p++) {
                int l = 2 * (p - 5);
                int j = p * 8 + tq * 2;
                float* aM = aG2[l];
                float* aU = aG2[l + 1];
                float2 w0 = *reinterpret_cast<const float2*>(Cw2 + r0 * 68 + j);
                float2 w1 = *reinterpret_cast<const float2*>(Cw2 + r1 * 68 + j);
                float2 h0 = *reinterpret_cast<float2*>(S + r0 * PS + 128 + j);
                float2 h1 = *reinterpret_cast<float2*>(S + r1 * PS + 128 + j);
                float cc0 = sB[128 + j], cc1 = sB[128 + j + 1];
                float ub0 = sB[192 + j], ub1 = sB[192 + j + 1];
                h0.x += ftanh(w0.x + aM[0] + cc0) + ftanh(aU[0] + ub0);
                h0.y += ftanh(w0.y + aM[1] + cc1) + ftanh(aU[1] + ub1);
                h1.x += ftanh(w1.x + aM[2] + cc0) + ftanh(aU[2] + ub0);
                h1.y += ftanh(w1.y + aM[3] + cc1) + ftanh(aU[3] + ub1);
                *reinterpret_cast<float2*>(S + r0 * PS + 128 + j) = h0;
                *reinterpret_cast<float2*>(S + r1 * PS + 128 + j) = h1;
            }
#pragma unroll
            for (int w = 0; w < 4; w++) {
                int l = 6 + w;
                int j = w * 8 + tq * 2;
                *reinterpret_cast<float2*>(Cw3 + r0 * 36 + j) = make_float2(aG2[l][0], aG2[l][1]);
                *reinterpret_cast<float2*>(Cw3 + r1 * 36 + j) = make_float2(aG2[l][2], aG2[l][3]);
            }
        }

        // ---- G3: A=h3 (K=32, k-off 192), 2 slots ----
        float aG3[4][4] = {};
#pragma unroll 1
        for (int c = 0; c < 2; c++) {
            uint2 pr[10];
            if (c < 1) pldP(g_G3h, g_G3l, 32, 64, 1, tid, pr, 2);
            else       pldP(g_G1h, g_G1l, 128, 320, 0, tid, pr, 10);
            gemmHM<4>(Ah, Al, cur, 64, 192 + c * 16, arow, nh, gid, tq, aG3);
            if (c < 1) pstP(oth, 64, tid, pr, 2);
            else       pstP(oth, 320, tid, pr, 10);
            __syncthreads();
            __nv_bfloat16* t = cur; cur = oth; oth = t;
        }

        // ---- epilogue 3: update h3 ----
        {
            int pbase = nh * 2;
#pragma unroll
            for (int q = 0; q < 2; q++) {
                int p = pbase + q;
                int l = 2 * q;
                int j = p * 8 + tq * 2;
                float* aM = aG3[l];
                float* aU = aG3[l + 1];
                float2 w0 = *reinterpret_cast<const float2*>(Cw3 + r0 * 36 + j);
                float2 w1 = *reinterpret_cast<const float2*>(Cw3 + r1 * 36 + j);
                float2 h0 = *reinterpret_cast<float2*>(S + r0 * PS + 192 + j);
                float2 h1 = *reinterpret_cast<float2*>(S + r1 * PS + 192 + j);
                float cc0 = sB[256 + j], cc1 = sB[256 + j + 1];
                float ub0 = sB[288 + j], ub1 = sB[288 + j + 1];
                h0.x += ftanh(w0.x + aM[0] + cc0) + ftanh(aU[0] + ub0);
                h0.y += ftanh(w0.y + aM[1] + cc1) + ftanh(aU[1] + ub1);
                h1.x += ftanh(w1.x + aM[2] + cc0) + ftanh(aU[2] + ub0);
                h1.y += ftanh(w1.y + aM[3] + cc1) + ftanh(aU[3] + ub1);
                *reinterpret_cast<float2*>(S + r0 * PS + 192 + j) = h0;
                *reinterpret_cast<float2*>(S + r1 * PS + 192 + j) = h1;
            }
        }
        __syncthreads();   // state writes visible to next step's conversion
    }

    // ---- classifier: out = h3 @ clf^T + clf_b ----
    for (int idx = tid; idx < BT * 10; idx += NTHR) {
        int r = idx / 10, cc = idx - r * 10;
        float sacc = clfb[cc];
#pragma unroll
        for (int k = 0; k < 32; k++) sacc += S[r * PS + 192 + k] * clfw[cc * 32 + k];
        out[(size_t)(row0 + r) * 10 + cc] = sacc;
    }
}

// ---------------- launch ----------------
extern "C" void kernel_launch(void* const* d_in, const int* in_sizes, int n_in,
                              void* d_out, int out_size) {
    const float* x    = (const float*)d_in[0];
    const float* W1w  = (const float*)d_in[1];
    const float* W1b  = (const float*)d_in[2];
    const float* U1w  = (const float*)d_in[3];
    const float* U1b  = (const float*)d_in[4];
    const float* W2w  = (const float*)d_in[5];
    const float* W2b  = (const float*)d_in[6];
    const float* U2w  = (const float*)d_in[7];
    const float* U2b  = (const float*)d_in[8];
    const float* W3w  = (const float*)d_in[9];
    const float* W3b  = (const float*)d_in[10];
    const float* U3w  = (const float*)d_in[11];
    const float* U3b  = (const float*)d_in[12];
    const float* fb3w = (const float*)d_in[13];
    const float* fb3b = (const float*)d_in[14];
    const float* fb2w = (const float*)d_in[15];
    const float* fb2b = (const float*)d_in[16];
    const float* fb1w = (const float*)d_in[17];
    const float* fb1b = (const float*)d_in[18];
    const float* clfw = (const float*)d_in[19];
    const float* clfb = (const float*)d_in[20];
    const int*   stp  = (const int*)d_in[21];

    int B = in_sizes[0] / 784;
    if (B > 65536) B = 65536;   // g_XW capacity guard

    prep_all<<<256, 128>>>(W1w, W1b, U1w, W2w, W2b, U2w, W3w, W3b, U3w,
                           fb3w, fb3b, fb2w, fb2b, fb1w, fb1b);

    const int p1_smem = 4 * 128 * PW * 2 + 512;   // 139776 B
    cudaFuncSetAttribute(phase1_mma, cudaFuncAttributeMaxDynamicSharedMemorySize, p1_smem);
    phase1_mma<<<B / 128, 256, p1_smem>>>(x);

    const int smem_bytes = 53568 * 4;   // 214272 B -> 1 CTA/SM
    cudaFuncSetAttribute(pcnet_main, cudaFuncAttributeMaxDynamicSharedMemorySize, smem_bytes);
    pcnet_main<<<B / BT, NTHR, smem_bytes>>>(U1b, U2b, U3b, clfw, clfb, stp, (float*)d_out);
}